// round 9
// baseline (speedup 1.0000x reference)
#include <cuda_runtime.h>
#include <cstdint>

#define BATCH 4
#define C 512
#define CQ 64
#define NPOS 4096

#define LOG2E 1.4426950408889634f
#define PSHIFT 6.0f

// ---------------- scratch (device globals) ----------------------------------
__device__ uint16_t g_qbT[(size_t)BATCH * NPOS * CQ];   // [b][n][o] f16, pre-scaled log2e
__device__ uint16_t g_kbT[(size_t)BATCH * NPOS * CQ];   // [b][m][o] f16
__device__ uint8_t  g_v [(size_t)BATCH * C * NPOS];     // [b][c][m] e4m3
__device__ uint8_t  g_P [(size_t)BATCH * NPOS * NPOS];  // [b][n][m] e4m3 2^(E'-6)
__device__ uint16_t g_xb[(size_t)BATCH * C * NPOS];     // [b][c][n] f16
__device__ float    g_sum[BATCH * NPOS];

// ---------------- helpers ----------------------------------------------------
__device__ __forceinline__ unsigned smem_u32(const void* p) {
    return (unsigned)__cvta_generic_to_shared(p);
}
__device__ __forceinline__ void cpa16(unsigned s, const void* g) {
    asm volatile("cp.async.cg.shared.global [%0], [%1], 16;\n" :: "r"(s), "l"(g));
}
__device__ __forceinline__ void cpcommit() { asm volatile("cp.async.commit_group;\n" ::); }
template <int n>
__device__ __forceinline__ void cpwait() { asm volatile("cp.async.wait_group %0;\n" :: "n"(n)); }

__device__ __forceinline__ uint32_t hpack(float lo, float hi) {
    uint32_t u;
    asm("cvt.rn.f16x2.f32 %0, %1, %2;" : "=r"(u) : "f"(hi), "f"(lo));
    return u;
}
__device__ __forceinline__ uint16_t h16of(float x) {
    uint16_t h;
    asm("cvt.rn.f16.f32 %0, %1;" : "=h"(h) : "f"(x));
    return h;
}
// two f32 -> e4m3x2 (lo in low byte)
__device__ __forceinline__ uint16_t epack(float lo, float hi) {
    uint16_t h;
    asm("cvt.rn.satfinite.e4m3x2.f32 %0, %1, %2;" : "=h"(h) : "f"(hi), "f"(lo));
    return h;
}
// f16x2 -> e4m3x2
__device__ __forceinline__ uint16_t e4ofh2(uint32_t h2) {
    uint16_t h;
    asm("cvt.rn.satfinite.e4m3x2.f16x2 %0, %1;" : "=h"(h) : "r"(h2));
    return h;
}
__device__ __forceinline__ uint32_t ex2h2(uint32_t x) {
    uint32_t d;
    asm("ex2.approx.f16x2 %0, %1;" : "=r"(d) : "r"(x));
    return d;
}
__device__ __forceinline__ void ldm_x4(uint32_t* r, uint32_t addr) {
    asm volatile("ldmatrix.sync.aligned.m8n8.x4.shared.b16 {%0,%1,%2,%3}, [%4];"
        : "=r"(r[0]), "=r"(r[1]), "=r"(r[2]), "=r"(r[3]) : "r"(addr));
}
__device__ __forceinline__ void ldm_x4_t(uint32_t* r, uint32_t addr) {
    asm volatile("ldmatrix.sync.aligned.m8n8.x4.trans.shared.b16 {%0,%1,%2,%3}, [%4];"
        : "=r"(r[0]), "=r"(r[1]), "=r"(r[2]), "=r"(r[3]) : "r"(addr));
}
__device__ __forceinline__ void mma_h(float* d, const uint32_t* a, const uint32_t* b) {
    asm volatile("mma.sync.aligned.m16n8k16.row.col.f32.f16.f16.f32 "
        "{%0,%1,%2,%3}, {%4,%5,%6,%7}, {%8,%9}, {%0,%1,%2,%3};"
        : "+f"(d[0]), "+f"(d[1]), "+f"(d[2]), "+f"(d[3])
        : "r"(a[0]), "r"(a[1]), "r"(a[2]), "r"(a[3]), "r"(b[0]), "r"(b[1]));
}
__device__ __forceinline__ void mma_e4(float* d, const uint32_t* a, const uint32_t* b) {
    asm volatile("mma.sync.aligned.m16n8k32.row.col.f32.e4m3.e4m3.f32 "
        "{%0,%1,%2,%3}, {%4,%5,%6,%7}, {%8,%9}, {%0,%1,%2,%3};"
        : "+f"(d[0]), "+f"(d[1]), "+f"(d[2]), "+f"(d[3])
        : "r"(a[0]), "r"(a[1]), "r"(a[2]), "r"(a[3]), "r"(b[0]), "r"(b[1]));
}

extern __shared__ __align__(16) char smem[];

// ---------------------------------------------------------------------------
// x (fp32) -> g_xb (f16); first 16384 threads also zero g_sum.
__global__ void cvt_x_kernel(const float* __restrict__ x) {
    int t = blockIdx.x * 256 + threadIdx.x;
    if (t < BATCH * NPOS) g_sum[t] = 0.f;
    size_t i = (size_t)t * 4;
    float4 v = *(const float4*)&x[i];
    uint2 o;
    o.x = hpack(v.x, v.y);
    o.y = hpack(v.z, v.w);
    *(uint2*)&g_xb[i] = o;
}

// ---------------------------------------------------------------------------
// Fused q/k projection (f16 mma). rows 0-63 = Wq (scaled by log2e), 64-127 = Wk.
// Epilogue stores TRANSPOSED f16 [n][o].
// ---------------------------------------------------------------------------
__global__ __launch_bounds__(256) void proj_qk_kernel(
    const float* __restrict__ Wq, const float* __restrict__ bq,
    const float* __restrict__ Wk, const float* __restrict__ bk)
{
    uint32_t sbase = smem_u32(smem);

    int tid = threadIdx.x, lane = tid & 31, wid = tid >> 5;
    int warp_mi = wid >> 2;        // 0 = q rows, 1 = k rows
    int warp_ni = wid & 3;
    int b = blockIdx.z;
    int n0 = blockIdx.x * 128;

    const uint16_t* X = g_xb + (size_t)b * C * NPOS;
    const int KT = C / 64;

    float aw[4][8];
    auto ldgA = [&](int kt) {
#pragma unroll
        for (int i = 0; i < 4; i++) {
            int idx = tid + i * 256;
            int r = idx >> 3, c = idx & 7;
            const float* src = (r < 64)
                ? Wq + (size_t)r * C + kt * 64 + c * 8
                : Wk + (size_t)(r - 64) * C + kt * 64 + c * 8;
            float4 v0 = *(const float4*)src;
            float4 v1 = *(const float4*)(src + 4);
            aw[i][0] = v0.x; aw[i][1] = v0.y; aw[i][2] = v0.z; aw[i][3] = v0.w;
            aw[i][4] = v1.x; aw[i][5] = v1.y; aw[i][6] = v1.z; aw[i][7] = v1.w;
        }
    };
    auto stsA = [&](int s) {
#pragma unroll
        for (int i = 0; i < 4; i++) {
            int idx = tid + i * 256;
            int r = idx >> 3, c = idx & 7;
            int cs = c ^ (r & 7);
            uint4 o;
            o.x = hpack(aw[i][0], aw[i][1]);
            o.y = hpack(aw[i][2], aw[i][3]);
            o.z = hpack(aw[i][4], aw[i][5]);
            o.w = hpack(aw[i][6], aw[i][7]);
            *(uint4*)(smem + s * 32768 + r * 128 + cs * 16) = o;
        }
    };
    auto cpaB = [&](int kt, int s) {
#pragma unroll
        for (int i = 0; i < 4; i++) {
            int idx = tid + i * 256;
            int r = idx >> 4, c = idx & 15;
            int cs = (c & 8) | ((c & 7) ^ (r & 7));
            cpa16(sbase + s * 32768 + 16384 + r * 256 + cs * 16,
                  X + (size_t)(kt * 64 + r) * NPOS + n0 + c * 8);
        }
        cpcommit();
    };

    float acc[4][4][4];
#pragma unroll
    for (int i = 0; i < 4; i++)
#pragma unroll
        for (int j = 0; j < 4; j++)
#pragma unroll
            for (int k = 0; k < 4; k++) acc[i][j][k] = 0.f;

    ldgA(0);
    cpaB(0, 0);
    stsA(0);

    for (int kt = 0; kt < KT; kt++) {
        cpwait<0>();
        __syncthreads();
        if (kt + 1 < KT) {
            cpaB(kt + 1, (kt + 1) & 1);
            ldgA(kt + 1);
        }
        uint32_t sA = sbase + (kt & 1) * 32768;
        uint32_t sB = sA + 16384;
#pragma unroll
        for (int ks = 0; ks < 4; ks++) {
            uint32_t a[4][4];
#pragma unroll
            for (int mi = 0; mi < 4; mi++) {
                int row = warp_mi * 64 + mi * 16 + (lane & 15);
                int ch = ks * 2 + (lane >> 4);
                int cs = ch ^ (row & 7);
                ldm_x4(a[mi], sA + row * 128 + cs * 16);
            }
            uint32_t bf[2][4];
#pragma unroll
            for (int nb = 0; nb < 2; nb++) {
                int krow = ks * 16 + (lane & 7) + ((lane >> 3) & 1) * 8;
                int nch = warp_ni * 4 + nb * 2 + (lane >> 4);
                int cs = (nch & 8) | ((nch & 7) ^ (krow & 7));
                ldm_x4_t(bf[nb], sB + krow * 256 + cs * 16);
            }
#pragma unroll
            for (int mi = 0; mi < 4; mi++)
#pragma unroll
                for (int ni = 0; ni < 4; ni++)
                    mma_h(acc[mi][ni], a[mi], &bf[ni >> 1][(ni & 1) * 2]);
        }
        if (kt + 1 < KT) stsA((kt + 1) & 1);
    }

    int g = lane >> 2, tq = lane & 3;
    uint16_t* Y = (warp_mi == 0 ? g_qbT : g_kbT) + (size_t)b * NPOS * CQ;
    float scale = (warp_mi == 0) ? LOG2E : 1.0f;
#pragma unroll
    for (int mi = 0; mi < 4; mi++) {
        int o0 = mi * 16 + g;
        int o1 = o0 + 8;
        float bv0 = (warp_mi == 0) ? bq[o0] : bk[o0];
        float bv1 = (warp_mi == 0) ? bq[o1] : bk[o1];
#pragma unroll
        for (int ni = 0; ni < 4; ni++) {
            int ncol = n0 + warp_ni * 32 + ni * 8 + 2 * tq;
            Y[(size_t)ncol * CQ + o0]       = h16of((acc[mi][ni][0] + bv0) * scale);
            Y[(size_t)(ncol + 1) * CQ + o0] = h16of((acc[mi][ni][1] + bv0) * scale);
            Y[(size_t)ncol * CQ + o1]       = h16of((acc[mi][ni][2] + bv1) * scale);
            Y[(size_t)(ncol + 1) * CQ + o1] = h16of((acc[mi][ni][3] + bv1) * scale);
        }
    }
}

// ---------------------------------------------------------------------------
// proj_v (f16 mma): V[c][n] = sum_k Wv[c][k]*xb[k][n] + bv[c], store e4m3.
// ---------------------------------------------------------------------------
__global__ __launch_bounds__(256) void proj_v_kernel(
    const float* __restrict__ W, const float* __restrict__ bias)
{
    uint32_t sbase = smem_u32(smem);

    int tid = threadIdx.x, lane = tid & 31, wid = tid >> 5;
    int warp_mi = wid >> 2;
    int warp_ni = wid & 3;
    int b = blockIdx.z;
    int n0 = blockIdx.x * 128, c0 = blockIdx.y * 128;

    const uint16_t* X = g_xb + (size_t)b * C * NPOS;
    const int KT = C / 64;

    float aw[4][8];
    auto ldgA = [&](int kt) {
#pragma unroll
        for (int i = 0; i < 4; i++) {
            int idx = tid + i * 256;
            int r = idx >> 3, c = idx & 7;
            const float* src = W + (size_t)(c0 + r) * C + kt * 64 + c * 8;
            float4 v0 = *(const float4*)src;
            float4 v1 = *(const float4*)(src + 4);
            aw[i][0] = v0.x; aw[i][1] = v0.y; aw[i][2] = v0.z; aw[i][3] = v0.w;
            aw[i][4] = v1.x; aw[i][5] = v1.y; aw[i][6] = v1.z; aw[i][7] = v1.w;
        }
    };
    auto stsA = [&](int s) {
#pragma unroll
        for (int i = 0; i < 4; i++) {
            int idx = tid + i * 256;
            int r = idx >> 3, c = idx & 7;
            int cs = c ^ (r & 7);
            uint4 o;
            o.x = hpack(aw[i][0], aw[i][1]);
            o.y = hpack(aw[i][2], aw[i][3]);
            o.z = hpack(aw[i][4], aw[i][5]);
            o.w = hpack(aw[i][6], aw[i][7]);
            *(uint4*)(smem + s * 32768 + r * 128 + cs * 16) = o;
        }
    };
    auto cpaB = [&](int kt, int s) {
#pragma unroll
        for (int i = 0; i < 4; i++) {
            int idx = tid + i * 256;
            int r = idx >> 4, c = idx & 15;
            int cs = (c & 8) | ((c & 7) ^ (r & 7));
            cpa16(sbase + s * 32768 + 16384 + r * 256 + cs * 16,
                  X + (size_t)(kt * 64 + r) * NPOS + n0 + c * 8);
        }
        cpcommit();
    };

    float acc[4][4][4];
#pragma unroll
    for (int i = 0; i < 4; i++)
#pragma unroll
        for (int j = 0; j < 4; j++)
#pragma unroll
            for (int k = 0; k < 4; k++) acc[i][j][k] = 0.f;

    ldgA(0);
    cpaB(0, 0);
    stsA(0);

    for (int kt = 0; kt < KT; kt++) {
        cpwait<0>();
        __syncthreads();
        if (kt + 1 < KT) {
            cpaB(kt + 1, (kt + 1) & 1);
            ldgA(kt + 1);
        }
        uint32_t sA = sbase + (kt & 1) * 32768;
        uint32_t sB = sA + 16384;
#pragma unroll
        for (int ks = 0; ks < 4; ks++) {
            uint32_t a[4][4];
#pragma unroll
            for (int mi = 0; mi < 4; mi++) {
                int row = warp_mi * 64 + mi * 16 + (lane & 15);
                int ch = ks * 2 + (lane >> 4);
                int cs = ch ^ (row & 7);
                ldm_x4(a[mi], sA + row * 128 + cs * 16);
            }
            uint32_t bf[2][4];
#pragma unroll
            for (int nb = 0; nb < 2; nb++) {
                int krow = ks * 16 + (lane & 7) + ((lane >> 3) & 1) * 8;
                int nch = warp_ni * 4 + nb * 2 + (lane >> 4);
                int cs = (nch & 8) | ((nch & 7) ^ (krow & 7));
                ldm_x4_t(bf[nb], sB + krow * 256 + cs * 16);
            }
#pragma unroll
            for (int mi = 0; mi < 4; mi++)
#pragma unroll
                for (int ni = 0; ni < 4; ni++)
                    mma_h(acc[mi][ni], a[mi], &bf[ni >> 1][(ni & 1) * 2]);
        }
        if (kt + 1 < KT) stsA((kt + 1) & 1);
    }

    int g = lane >> 2, tq = lane & 3;
    uint8_t* Vout = g_v + (size_t)b * C * NPOS;
#pragma unroll
    for (int mi = 0; mi < 4; mi++) {
        int c_r0 = c0 + warp_mi * 64 + mi * 16 + g;
        int c_r1 = c_r0 + 8;
        float bv0 = bias[c_r0], bv1 = bias[c_r1];
#pragma unroll
        for (int ni = 0; ni < 4; ni++) {
            int ncol = n0 + warp_ni * 32 + ni * 8 + 2 * tq;
            *(uint16_t*)&Vout[(size_t)c_r0 * NPOS + ncol] =
                epack(acc[mi][ni][0] + bv0, acc[mi][ni][1] + bv0);
            *(uint16_t*)&Vout[(size_t)c_r1 * NPOS + ncol] =
                epack(acc[mi][ni][2] + bv1, acc[mi][ni][3] + bv1);
        }
    }
}

// ---------------------------------------------------------------------------
// Energy (f16 mma): acc[n][m] = E*log2e (q pre-scaled). Epilogue:
// Pf16 = 2^(acc-6) via ex2.approx.f16x2; row sums via mma-with-ones;
// store P as e4m3.
// ---------------------------------------------------------------------------
__global__ __launch_bounds__(256) void energy_kernel()
{
    uint32_t sA = smem_u32(smem);
    uint32_t sB = sA + 16384;

    int tid = threadIdx.x, lane = tid & 31, wid = tid >> 5;
    int warp_mi = wid >> 2;        // n-dim (2 x 64)
    int warp_ni = wid & 3;         // m-dim (4 x 32)
    int b = blockIdx.z;
    int m0 = blockIdx.x * 128, n0 = blockIdx.y * 128;

    const uint16_t* Aq = g_qbT + ((size_t)b * NPOS + n0) * CQ;
    const uint16_t* Bk = g_kbT + ((size_t)b * NPOS + m0) * CQ;

#pragma unroll
    for (int i = 0; i < 4; i++) {
        int idx = i * 256 + tid;
        int r = idx >> 3, c = idx & 7;
        int cs = c ^ (r & 7);
        cpa16(sA + r * 128 + cs * 16, Aq + (size_t)r * CQ + c * 8);
        cpa16(sB + r * 128 + cs * 16, Bk + (size_t)r * CQ + c * 8);
    }
    cpcommit();
    cpwait<0>();
    __syncthreads();

    float acc[4][4][4];
#pragma unroll
    for (int i = 0; i < 4; i++)
#pragma unroll
        for (int j = 0; j < 4; j++)
#pragma unroll
            for (int k = 0; k < 4; k++) acc[i][j][k] = 0.f;

    int a_row_b = warp_mi * 64 + (lane & 15);
    int a_cadd = lane >> 4;
    int b_row_b = warp_ni * 32 + (lane & 7) + ((lane >> 4) << 3);
    int b_cadd = (lane >> 3) & 1;

#pragma unroll
    for (int ks = 0; ks < 4; ks++) {
        int kc = ks * 2;
        uint32_t a[4][4];
#pragma unroll
        for (int mi = 0; mi < 4; mi++) {
            int row = a_row_b + mi * 16;
            int cs = (kc + a_cadd) ^ (row & 7);
            ldm_x4(a[mi], sA + row * 128 + cs * 16);
        }
        uint32_t bf[2][4];
#pragma unroll
        for (int j2 = 0; j2 < 2; j2++) {
            int row = b_row_b + j2 * 16;
            int cs = (kc + b_cadd) ^ (row & 7);
            ldm_x4(bf[j2], sB + row * 128 + cs * 16);
        }
#pragma unroll
        for (int mi = 0; mi < 4; mi++)
#pragma unroll
            for (int ni = 0; ni < 4; ni++)
                mma_h(acc[mi][ni], a[mi], &bf[ni >> 1][(ni & 1) * 2]);
    }

    int g = lane >> 2, tq = lane & 3;
    uint8_t* Pout = g_P + (size_t)b * NPOS * NPOS;
    float* SUM = g_sum + b * NPOS;
    uint32_t onesb[2] = {0x3C003C00u, 0x3C003C00u};

#pragma unroll
    for (int mi = 0; mi < 4; mi++) {
        int r0 = n0 + warp_mi * 64 + mi * 16 + g;
        int r1 = r0 + 8;
        uint32_t e01[4], e23[4];
#pragma unroll
        for (int ni = 0; ni < 4; ni++) {
            e01[ni] = ex2h2(hpack(acc[mi][ni][0] - PSHIFT, acc[mi][ni][1] - PSHIFT));
            e23[ni] = ex2h2(hpack(acc[mi][ni][2] - PSHIFT, acc[mi][ni][3] - PSHIFT));
            int col = m0 + warp_ni * 32 + ni * 8 + 2 * tq;
            *(uint16_t*)&Pout[(size_t)r0 * NPOS + col] = e4ofh2(e01[ni]);
            *(uint16_t*)&Pout[(size_t)r1 * NPOS + col] = e4ofh2(e23[ni]);
        }
        float ss[4] = {0.f, 0.f, 0.f, 0.f};
        uint32_t A0[4] = {e01[0], e23[0], e01[1], e23[1]};
        uint32_t A1[4] = {e01[2], e23[2], e01[3], e23[3]};
        mma_h(ss, A0, onesb);
        mma_h(ss, A1, onesb);
        if (tq == 0) {
            atomicAdd(&SUM[r0], ss[0]);
            atomicAdd(&SUM[r1], ss[2]);
        }
    }
}

// ---------------------------------------------------------------------------
// Out (e4m3 mma k32, 256x128 tile, 3-stage): D[c][n] = sum_m V[c][m]*P[n][m]
// Epilogue: out = gamma*(1/sum[n])*D + x. blockIdx.x = c-block (L2 pairing).
// ---------------------------------------------------------------------------
__global__ __launch_bounds__(256) void out_kernel(
    const float* __restrict__ x, const float* __restrict__ gamma,
    float* __restrict__ out)
{
    uint32_t sbase = smem_u32(smem);

    int tid = threadIdx.x, lane = tid & 31, wid = tid >> 5;
    int warp_mi = wid >> 1;        // c-dim (4 x 64)
    int warp_ni = wid & 1;         // n-dim (2 x 64)
    int b = blockIdx.z;
    int n0 = blockIdx.y * 128, c0 = blockIdx.x * 256;

    const uint8_t* V = g_v + ((size_t)b * C + c0) * NPOS;
    const uint8_t* P = g_P + ((size_t)b * NPOS + n0) * NPOS;

    const int KT = NPOS / 128;     // 32 k-tiles of 128 fp8
    const int STG = 49152;         // 32KB A + 16KB B per stage

    auto load_stage = [&](int s, int kt) {
        int mb = kt * 128;
        uint32_t st = sbase + s * STG;
#pragma unroll
        for (int i = 0; i < 8; i++) {          // A: 256 rows x 128B
            int idx = i * 256 + tid;
            int r = idx >> 3, c = idx & 7;
            int cs = c ^ (r & 7);
            cpa16(st + r * 128 + cs * 16, V + (size_t)r * NPOS + mb + c * 16);
        }
#pragma unroll
        for (int i = 0; i < 4; i++) {          // B: 128 rows x 128B
            int idx = i * 256 + tid;
            int r = idx >> 3, c = idx & 7;
            int cs = c ^ (r & 7);
            cpa16(st + 32768 + r * 128 + cs * 16, P + (size_t)r * NPOS + mb + c * 16);
        }
        cpcommit();
    };

    load_stage(0, 0);
    load_stage(1, 1);

    float acc[4][8][4];
#pragma unroll
    for (int i = 0; i < 4; i++)
#pragma unroll
        for (int j = 0; j < 8; j++)
#pragma unroll
            for (int k = 0; k < 4; k++) acc[i][j][k] = 0.f;

    int a_row_b = warp_mi * 64 + (lane & 15);
    int a_cadd = lane >> 4;
    int b_row_b = warp_ni * 64 + (lane & 7) + ((lane >> 4) << 3);
    int b_cadd = (lane >> 3) & 1;

    for (int kt = 0; kt < KT; kt++) {
        if (kt >= KT - 1) cpwait<0>(); else cpwait<1>();
        __syncthreads();
        if (kt + 2 < KT) load_stage((kt + 2) % 3, kt + 2);

        uint32_t sA = sbase + (kt % 3) * STG;
        uint32_t sB = sA + 32768;
#pragma unroll
        for (int ks = 0; ks < 4; ks++) {       // each ks = k32 fp8 = 2 chunks
            int kc = ks * 2;
            uint32_t a[4][4];
#pragma unroll
            for (int mi = 0; mi < 4; mi++) {
                int row = a_row_b + mi * 16;
                int cs = (kc + a_cadd) ^ (row & 7);
                ldm_x4(a[mi], sA + row * 128 + cs * 16);
            }
            uint32_t bf[4][4];
#pragma unroll
            for (int j2 = 0; j2 < 4; j2++) {
                int row = b_row_b + j2 * 16;
                int cs = (kc + b_cadd) ^ (row & 7);
                ldm_x4(bf[j2], sB + row * 128 + cs * 16);
            }
#pragma unroll
            for (int mi = 0; mi < 4; mi++)
#pragma unroll
                for (int ni = 0; ni < 8; ni++)
                    mma_e4(acc[mi][ni], a[mi], &bf[ni >> 1][(ni & 1) * 2]);
        }
    }

    int g = lane >> 2, tq = lane & 3;
    float gm = gamma[0];
    float2 iv[8];
#pragma unroll
    for (int ni = 0; ni < 8; ni++) {
        int ncol = n0 + warp_ni * 64 + ni * 8 + 2 * tq;
        float2 sv = *(const float2*)&g_sum[b * NPOS + ncol];
        iv[ni].x = 1.f / sv.x;
        iv[ni].y = 1.f / sv.y;
    }

#pragma unroll
    for (int mi = 0; mi < 4; mi++) {
        int c_r0 = c0 + warp_mi * 64 + mi * 16 + g;
        int c_r1 = c_r0 + 8;
#pragma unroll
        for (int ni = 0; ni < 8; ni++) {
            int ncol = n0 + warp_ni * 64 + ni * 8 + 2 * tq;
            size_t off0 = ((size_t)b * C + c_r0) * NPOS + ncol;
            size_t off1 = ((size_t)b * C + c_r1) * NPOS + ncol;
            float2 xv0 = *(const float2*)&x[off0];
            float2 xv1 = *(const float2*)&x[off1];
            float2 o0, o1;
            o0.x = gm * iv[ni].x * acc[mi][ni][0] + xv0.x;
            o0.y = gm * iv[ni].y * acc[mi][ni][1] + xv0.y;
            o1.x = gm * iv[ni].x * acc[mi][ni][2] + xv1.x;
            o1.y = gm * iv[ni].y * acc[mi][ni][3] + xv1.y;
            *(float2*)&out[off0] = o0;
            *(float2*)&out[off1] = o1;
        }
    }
}

// ---------------------------------------------------------------------------
extern "C" void kernel_launch(void* const* d_in, const int* in_sizes, int n_in,
                              void* d_out, int out_size)
{
    const float* x     = (const float*)d_in[0];
    const float* Wq    = (const float*)d_in[1];
    const float* bq    = (const float*)d_in[2];
    const float* Wk    = (const float*)d_in[3];
    const float* bk    = (const float*)d_in[4];
    const float* Wv    = (const float*)d_in[5];
    const float* bv    = (const float*)d_in[6];
    const float* gamma = (const float*)d_in[7];
    float* out = (float*)d_out;

    cudaFuncSetAttribute(proj_qk_kernel,
                         cudaFuncAttributeMaxDynamicSharedMemorySize, 65536);
    cudaFuncSetAttribute(proj_v_kernel,
                         cudaFuncAttributeMaxDynamicSharedMemorySize, 65536);
    cudaFuncSetAttribute(energy_kernel,
                         cudaFuncAttributeMaxDynamicSharedMemorySize, 32768);
    cudaFuncSetAttribute(out_kernel,
                         cudaFuncAttributeMaxDynamicSharedMemorySize, 147456);

    cvt_x_kernel<<<(int)((size_t)BATCH * C * NPOS / 4 / 256), 256>>>(x);

    proj_qk_kernel<<<dim3(NPOS / 128, 1, BATCH), 256, 65536>>>(Wq, bq, Wk, bk);
    proj_v_kernel<<<dim3(NPOS / 128, C / 128, BATCH), 256, 65536>>>(Wv, bv);

    energy_kernel<<<dim3(NPOS / 128, NPOS / 128, BATCH), 256, 32768>>>();

    out_kernel<<<dim3(C / 256, NPOS / 128, BATCH), 256, 147456>>>(x, gamma, out);
}

// round 11
// speedup vs baseline: 1.0634x; 1.0634x over previous
#include <cuda_runtime.h>
#include <cstdint>

#define BATCH 4
#define C 512
#define CQ 64
#define NPOS 4096

#define LOG2E 1.4426950408889634f
#define PSHIFT 4.0f
#define MB 4                       // m-tiles per energy CTA

// ---------------- scratch (device globals) ----------------------------------
__device__ uint16_t g_qbT[(size_t)BATCH * NPOS * CQ];   // [b][n][o] f16, pre-scaled log2e
__device__ uint16_t g_kbT[(size_t)BATCH * NPOS * CQ];   // [b][m][o] f16
__device__ uint16_t g_v [(size_t)BATCH * C * NPOS];     // [b][c][m] f16
__device__ uint16_t g_P [(size_t)BATCH * NPOS * NPOS];  // [b][n][m] f16 2^(E'-4)
__device__ uint16_t g_xb[(size_t)BATCH * C * NPOS];     // [b][c][n] f16
__device__ float    g_sum[BATCH * NPOS];

// ---------------- helpers ----------------------------------------------------
__device__ __forceinline__ unsigned smem_u32(const void* p) {
    return (unsigned)__cvta_generic_to_shared(p);
}
__device__ __forceinline__ void cpa16(unsigned s, const void* g) {
    asm volatile("cp.async.cg.shared.global [%0], [%1], 16;\n" :: "r"(s), "l"(g));
}
__device__ __forceinline__ void cpcommit() { asm volatile("cp.async.commit_group;\n" ::); }
template <int n>
__device__ __forceinline__ void cpwait() { asm volatile("cp.async.wait_group %0;\n" :: "n"(n)); }

__device__ __forceinline__ uint32_t hpack(float lo, float hi) {
    uint32_t u;
    asm("cvt.rn.f16x2.f32 %0, %1, %2;" : "=r"(u) : "f"(hi), "f"(lo));
    return u;
}
__device__ __forceinline__ uint16_t h16of(float x) {
    uint16_t h;
    asm("cvt.rn.f16.f32 %0, %1;" : "=h"(h) : "f"(x));
    return h;
}
__device__ __forceinline__ uint32_t ex2h2(uint32_t x) {
    uint32_t d;
    asm("ex2.approx.f16x2 %0, %1;" : "=r"(d) : "r"(x));
    return d;
}
__device__ __forceinline__ void ldm_x4(uint32_t* r, uint32_t addr) {
    asm volatile("ldmatrix.sync.aligned.m8n8.x4.shared.b16 {%0,%1,%2,%3}, [%4];"
        : "=r"(r[0]), "=r"(r[1]), "=r"(r[2]), "=r"(r[3]) : "r"(addr));
}
__device__ __forceinline__ void ldm_x4_t(uint32_t* r, uint32_t addr) {
    asm volatile("ldmatrix.sync.aligned.m8n8.x4.trans.shared.b16 {%0,%1,%2,%3}, [%4];"
        : "=r"(r[0]), "=r"(r[1]), "=r"(r[2]), "=r"(r[3]) : "r"(addr));
}
__device__ __forceinline__ void mma_h(float* d, const uint32_t* a, const uint32_t* b) {
    asm volatile("mma.sync.aligned.m16n8k16.row.col.f32.f16.f16.f32 "
        "{%0,%1,%2,%3}, {%4,%5,%6,%7}, {%8,%9}, {%0,%1,%2,%3};"
        : "+f"(d[0]), "+f"(d[1]), "+f"(d[2]), "+f"(d[3])
        : "r"(a[0]), "r"(a[1]), "r"(a[2]), "r"(a[3]), "r"(b[0]), "r"(b[1]));
}

extern __shared__ __align__(16) char smem[];

// ---------------------------------------------------------------------------
// x (fp32) -> g_xb (f16); first 16384 threads also zero g_sum.
__global__ void cvt_x_kernel(const float* __restrict__ x) {
    int t = blockIdx.x * 256 + threadIdx.x;
    if (t < BATCH * NPOS) g_sum[t] = 0.f;
    size_t i = (size_t)t * 4;
    float4 v = *(const float4*)&x[i];
    uint2 o;
    o.x = hpack(v.x, v.y);
    o.y = hpack(v.z, v.w);
    *(uint2*)&g_xb[i] = o;
}

// ---------------------------------------------------------------------------
// Fused q/k projection (f16 mma). rows 0-63 = Wq (scaled by log2e), 64-127 = Wk.
// Epilogue stores TRANSPOSED f16 [n][o].
// ---------------------------------------------------------------------------
__global__ __launch_bounds__(256) void proj_qk_kernel(
    const float* __restrict__ Wq, const float* __restrict__ bq,
    const float* __restrict__ Wk, const float* __restrict__ bk)
{
    uint32_t sbase = smem_u32(smem);

    int tid = threadIdx.x, lane = tid & 31, wid = tid >> 5;
    int warp_mi = wid >> 2;        // 0 = q rows, 1 = k rows
    int warp_ni = wid & 3;
    int b = blockIdx.z;
    int n0 = blockIdx.x * 128;

    const uint16_t* X = g_xb + (size_t)b * C * NPOS;
    const int KT = C / 64;

    float aw[4][8];
    auto ldgA = [&](int kt) {
#pragma unroll
        for (int i = 0; i < 4; i++) {
            int idx = tid + i * 256;
            int r = idx >> 3, c = idx & 7;
            const float* src = (r < 64)
                ? Wq + (size_t)r * C + kt * 64 + c * 8
                : Wk + (size_t)(r - 64) * C + kt * 64 + c * 8;
            float4 v0 = *(const float4*)src;
            float4 v1 = *(const float4*)(src + 4);
            aw[i][0] = v0.x; aw[i][1] = v0.y; aw[i][2] = v0.z; aw[i][3] = v0.w;
            aw[i][4] = v1.x; aw[i][5] = v1.y; aw[i][6] = v1.z; aw[i][7] = v1.w;
        }
    };
    auto stsA = [&](int s) {
#pragma unroll
        for (int i = 0; i < 4; i++) {
            int idx = tid + i * 256;
            int r = idx >> 3, c = idx & 7;
            int cs = c ^ (r & 7);
            uint4 o;
            o.x = hpack(aw[i][0], aw[i][1]);
            o.y = hpack(aw[i][2], aw[i][3]);
            o.z = hpack(aw[i][4], aw[i][5]);
            o.w = hpack(aw[i][6], aw[i][7]);
            *(uint4*)(smem + s * 32768 + r * 128 + cs * 16) = o;
        }
    };
    auto cpaB = [&](int kt, int s) {
#pragma unroll
        for (int i = 0; i < 4; i++) {
            int idx = tid + i * 256;
            int r = idx >> 4, c = idx & 15;
            int cs = (c & 8) | ((c & 7) ^ (r & 7));
            cpa16(sbase + s * 32768 + 16384 + r * 256 + cs * 16,
                  X + (size_t)(kt * 64 + r) * NPOS + n0 + c * 8);
        }
        cpcommit();
    };

    float acc[4][4][4];
#pragma unroll
    for (int i = 0; i < 4; i++)
#pragma unroll
        for (int j = 0; j < 4; j++)
#pragma unroll
            for (int k = 0; k < 4; k++) acc[i][j][k] = 0.f;

    ldgA(0);
    cpaB(0, 0);
    stsA(0);

    for (int kt = 0; kt < KT; kt++) {
        cpwait<0>();
        __syncthreads();
        if (kt + 1 < KT) {
            cpaB(kt + 1, (kt + 1) & 1);
            ldgA(kt + 1);
        }
        uint32_t sA = sbase + (kt & 1) * 32768;
        uint32_t sB = sA + 16384;
#pragma unroll
        for (int ks = 0; ks < 4; ks++) {
            uint32_t a[4][4];
#pragma unroll
            for (int mi = 0; mi < 4; mi++) {
                int row = warp_mi * 64 + mi * 16 + (lane & 15);
                int ch = ks * 2 + (lane >> 4);
                int cs = ch ^ (row & 7);
                ldm_x4(a[mi], sA + row * 128 + cs * 16);
            }
            uint32_t bf[2][4];
#pragma unroll
            for (int nb = 0; nb < 2; nb++) {
                int krow = ks * 16 + (lane & 7) + ((lane >> 3) & 1) * 8;
                int nch = warp_ni * 4 + nb * 2 + (lane >> 4);
                int cs = (nch & 8) | ((nch & 7) ^ (krow & 7));
                ldm_x4_t(bf[nb], sB + krow * 256 + cs * 16);
            }
#pragma unroll
            for (int mi = 0; mi < 4; mi++)
#pragma unroll
                for (int ni = 0; ni < 4; ni++)
                    mma_h(acc[mi][ni], a[mi], &bf[ni >> 1][(ni & 1) * 2]);
        }
        if (kt + 1 < KT) stsA((kt + 1) & 1);
    }

    int g = lane >> 2, tq = lane & 3;
    uint16_t* Y = (warp_mi == 0 ? g_qbT : g_kbT) + (size_t)b * NPOS * CQ;
    float scale = (warp_mi == 0) ? LOG2E : 1.0f;
#pragma unroll
    for (int mi = 0; mi < 4; mi++) {
        int o0 = mi * 16 + g;
        int o1 = o0 + 8;
        float bv0 = (warp_mi == 0) ? bq[o0] : bk[o0];
        float bv1 = (warp_mi == 0) ? bq[o1] : bk[o1];
#pragma unroll
        for (int ni = 0; ni < 4; ni++) {
            int ncol = n0 + warp_ni * 32 + ni * 8 + 2 * tq;
            Y[(size_t)ncol * CQ + o0]       = h16of((acc[mi][ni][0] + bv0) * scale);
            Y[(size_t)(ncol + 1) * CQ + o0] = h16of((acc[mi][ni][1] + bv0) * scale);
            Y[(size_t)ncol * CQ + o1]       = h16of((acc[mi][ni][2] + bv1) * scale);
            Y[(size_t)(ncol + 1) * CQ + o1] = h16of((acc[mi][ni][3] + bv1) * scale);
        }
    }
}

// ---------------------------------------------------------------------------
// proj_v (f16 mma): V[c][n] = sum_k Wv[c][k]*xb[k][n] + bv[c], store f16.
// ---------------------------------------------------------------------------
__global__ __launch_bounds__(256) void proj_v_kernel(
    const float* __restrict__ W, const float* __restrict__ bias)
{
    uint32_t sbase = smem_u32(smem);

    int tid = threadIdx.x, lane = tid & 31, wid = tid >> 5;
    int warp_mi = wid >> 2;
    int warp_ni = wid & 3;
    int b = blockIdx.z;
    int n0 = blockIdx.x * 128, c0 = blockIdx.y * 128;

    const uint16_t* X = g_xb + (size_t)b * C * NPOS;
    const int KT = C / 64;

    float aw[4][8];
    auto ldgA = [&](int kt) {
#pragma unroll
        for (int i = 0; i < 4; i++) {
            int idx = tid + i * 256;
            int r = idx >> 3, c = idx & 7;
            const float* src = W + (size_t)(c0 + r) * C + kt * 64 + c * 8;
            float4 v0 = *(const float4*)src;
            float4 v1 = *(const float4*)(src + 4);
            aw[i][0] = v0.x; aw[i][1] = v0.y; aw[i][2] = v0.z; aw[i][3] = v0.w;
            aw[i][4] = v1.x; aw[i][5] = v1.y; aw[i][6] = v1.z; aw[i][7] = v1.w;
        }
    };
    auto stsA = [&](int s) {
#pragma unroll
        for (int i = 0; i < 4; i++) {
            int idx = tid + i * 256;
            int r = idx >> 3, c = idx & 7;
            int cs = c ^ (r & 7);
            uint4 o;
            o.x = hpack(aw[i][0], aw[i][1]);
            o.y = hpack(aw[i][2], aw[i][3]);
            o.z = hpack(aw[i][4], aw[i][5]);
            o.w = hpack(aw[i][6], aw[i][7]);
            *(uint4*)(smem + s * 32768 + r * 128 + cs * 16) = o;
        }
    };
    auto cpaB = [&](int kt, int s) {
#pragma unroll
        for (int i = 0; i < 4; i++) {
            int idx = tid + i * 256;
            int r = idx >> 4, c = idx & 15;
            int cs = (c & 8) | ((c & 7) ^ (r & 7));
            cpa16(sbase + s * 32768 + 16384 + r * 256 + cs * 16,
                  X + (size_t)(kt * 64 + r) * NPOS + n0 + c * 8);
        }
        cpcommit();
    };

    float acc[4][4][4];
#pragma unroll
    for (int i = 0; i < 4; i++)
#pragma unroll
        for (int j = 0; j < 4; j++)
#pragma unroll
            for (int k = 0; k < 4; k++) acc[i][j][k] = 0.f;

    ldgA(0);
    cpaB(0, 0);
    stsA(0);

    for (int kt = 0; kt < KT; kt++) {
        cpwait<0>();
        __syncthreads();
        if (kt + 1 < KT) {
            cpaB(kt + 1, (kt + 1) & 1);
            ldgA(kt + 1);
        }
        uint32_t sA = sbase + (kt & 1) * 32768;
        uint32_t sB = sA + 16384;
#pragma unroll
        for (int ks = 0; ks < 4; ks++) {
            uint32_t a[4][4];
#pragma unroll
            for (int mi = 0; mi < 4; mi++) {
                int row = warp_mi * 64 + mi * 16 + (lane & 15);
                int ch = ks * 2 + (lane >> 4);
                int cs = ch ^ (row & 7);
                ldm_x4(a[mi], sA + row * 128 + cs * 16);
            }
            uint32_t bf[2][4];
#pragma unroll
            for (int nb = 0; nb < 2; nb++) {
                int krow = ks * 16 + (lane & 7) + ((lane >> 3) & 1) * 8;
                int nch = warp_ni * 4 + nb * 2 + (lane >> 4);
                int cs = (nch & 8) | ((nch & 7) ^ (krow & 7));
                ldm_x4_t(bf[nb], sB + krow * 256 + cs * 16);
            }
#pragma unroll
            for (int mi = 0; mi < 4; mi++)
#pragma unroll
                for (int ni = 0; ni < 4; ni++)
                    mma_h(acc[mi][ni], a[mi], &bf[ni >> 1][(ni & 1) * 2]);
        }
        if (kt + 1 < KT) stsA((kt + 1) & 1);
    }

    int g = lane >> 2, tq = lane & 3;
    uint16_t* Vout = g_v + (size_t)b * C * NPOS;
#pragma unroll
    for (int mi = 0; mi < 4; mi++) {
        int c_r0 = c0 + warp_mi * 64 + mi * 16 + g;
        int c_r1 = c_r0 + 8;
        float bv0 = bias[c_r0], bv1 = bias[c_r1];
#pragma unroll
        for (int ni = 0; ni < 4; ni++) {
            int ncol = n0 + warp_ni * 32 + ni * 8 + 2 * tq;
            *(uint32_t*)&Vout[(size_t)c_r0 * NPOS + ncol] =
                hpack(acc[mi][ni][0] + bv0, acc[mi][ni][1] + bv0);
            *(uint32_t*)&Vout[(size_t)c_r1 * NPOS + ncol] =
                hpack(acc[mi][ni][2] + bv1, acc[mi][ni][3] + bv1);
        }
    }
}

// ---------------------------------------------------------------------------
// Energy (f16 mma, persistent m-loop): CTA keeps q-tile (A) resident, loops
// over MB=4 key-tiles with double-buffered B loads. acc = E*log2e; epilogue
// P = 2^(acc-4) via ex2.f16x2, row-sum mma-with-ones ACCUMULATED across
// m-tiles, single atomicAdd at the end. smem: A 16KB + 2x B 16KB = 48KB.
// ---------------------------------------------------------------------------
__global__ __launch_bounds__(256) void energy_kernel()
{
    uint32_t sA = smem_u32(smem);
    uint32_t sB0 = sA + 16384;

    int tid = threadIdx.x, lane = tid & 31, wid = tid >> 5;
    int warp_mi = wid >> 2;        // n-dim (2 x 64)
    int warp_ni = wid & 3;         // m-dim (4 x 32)
    int b = blockIdx.z;
    int n0 = blockIdx.y * 128;
    int mbase = blockIdx.x * (MB * 128);

    const uint16_t* Aq = g_qbT + ((size_t)b * NPOS + n0) * CQ;
    const uint16_t* Bk = g_kbT + (size_t)b * NPOS * CQ;

    auto cpaB = [&](int m0, uint32_t dst) {
#pragma unroll
        for (int i = 0; i < 4; i++) {
            int idx = i * 256 + tid;
            int r = idx >> 3, c = idx & 7;
            int cs = c ^ (r & 7);
            cpa16(dst + r * 128 + cs * 16, Bk + (size_t)(m0 + r) * CQ + c * 8);
        }
        cpcommit();
    };

    // A tile + first B tile (one group)
#pragma unroll
    for (int i = 0; i < 4; i++) {
        int idx = i * 256 + tid;
        int r = idx >> 3, c = idx & 7;
        int cs = c ^ (r & 7);
        cpa16(sA + r * 128 + cs * 16, Aq + (size_t)r * CQ + c * 8);
    }
    cpaB(mbase, sB0);

    int a_row_b = warp_mi * 64 + (lane & 15);
    int a_cadd = lane >> 4;
    int b_row_b = warp_ni * 32 + (lane & 7) + ((lane >> 4) << 3);
    int b_cadd = (lane >> 3) & 1;
    int g = lane >> 2, tq = lane & 3;

    uint16_t* Pout = g_P + (size_t)b * NPOS * NPOS;
    uint32_t onesb[2] = {0x3C003C00u, 0x3C003C00u};
    float ssum[4][4];
#pragma unroll
    for (int i = 0; i < 4; i++)
#pragma unroll
        for (int k = 0; k < 4; k++) ssum[i][k] = 0.f;

    for (int mt = 0; mt < MB; mt++) {
        int m0 = mbase + mt * 128;
        uint32_t sB = sB0 + (mt & 1) * 16384;

        cpwait<0>();
        __syncthreads();
        if (mt + 1 < MB)
            cpaB(m0 + 128, sB0 + ((mt + 1) & 1) * 16384);

        float acc[4][4][4];
#pragma unroll
        for (int i = 0; i < 4; i++)
#pragma unroll
            for (int j = 0; j < 4; j++)
#pragma unroll
                for (int k = 0; k < 4; k++) acc[i][j][k] = 0.f;

#pragma unroll
        for (int ks = 0; ks < 4; ks++) {
            int kc = ks * 2;
            uint32_t a[4][4];
#pragma unroll
            for (int mi = 0; mi < 4; mi++) {
                int row = a_row_b + mi * 16;
                int cs = (kc + a_cadd) ^ (row & 7);
                ldm_x4(a[mi], sA + row * 128 + cs * 16);
            }
            uint32_t bf[2][4];
#pragma unroll
            for (int j2 = 0; j2 < 2; j2++) {
                int row = b_row_b + j2 * 16;
                int cs = (kc + b_cadd) ^ (row & 7);
                ldm_x4(bf[j2], sB + row * 128 + cs * 16);
            }
#pragma unroll
            for (int mi = 0; mi < 4; mi++)
#pragma unroll
                for (int ni = 0; ni < 4; ni++)
                    mma_h(acc[mi][ni], a[mi], &bf[ni >> 1][(ni & 1) * 2]);
        }

        // epilogue for this m-tile: exp2, store P, accumulate row sums
#pragma unroll
        for (int mi = 0; mi < 4; mi++) {
            int r0 = n0 + warp_mi * 64 + mi * 16 + g;
            int r1 = r0 + 8;
            uint32_t e01[4], e23[4];
#pragma unroll
            for (int ni = 0; ni < 4; ni++) {
                e01[ni] = ex2h2(hpack(acc[mi][ni][0] - PSHIFT, acc[mi][ni][1] - PSHIFT));
                e23[ni] = ex2h2(hpack(acc[mi][ni][2] - PSHIFT, acc[mi][ni][3] - PSHIFT));
                int col = m0 + warp_ni * 32 + ni * 8 + 2 * tq;
                *(uint32_t*)&Pout[(size_t)r0 * NPOS + col] = e01[ni];
                *(uint32_t*)&Pout[(size_t)r1 * NPOS + col] = e23[ni];
            }
            uint32_t A0[4] = {e01[0], e23[0], e01[1], e23[1]};
            uint32_t A1[4] = {e01[2], e23[2], e01[3], e23[3]};
            mma_h(ssum[mi], A0, onesb);
            mma_h(ssum[mi], A1, onesb);
        }
        __syncthreads();   // all warps done reading sB before it is overwritten
    }

    if (tq == 0) {
        float* SUM = g_sum + b * NPOS;
#pragma unroll
        for (int mi = 0; mi < 4; mi++) {
            int r0 = n0 + warp_mi * 64 + mi * 16 + g;
            atomicAdd(&SUM[r0], ssum[mi][0]);
            atomicAdd(&SUM[r0 + 8], ssum[mi][2]);
        }
    }
}

// ---------------------------------------------------------------------------
// Out (f16 mma, 256x128 tile, 3-stage): D[c][n] = sum_m V[c][m]*P[n][m]
// Epilogue: out = gamma*(1/sum[n])*D + x.
// ---------------------------------------------------------------------------
__global__ __launch_bounds__(256) void out_kernel(
    const float* __restrict__ x, const float* __restrict__ gamma,
    float* __restrict__ out)
{
    uint32_t sbase = smem_u32(smem);

    int tid = threadIdx.x, lane = tid & 31, wid = tid >> 5;
    int warp_mi = wid >> 1;        // c-dim (4 x 64)
    int warp_ni = wid & 1;         // n-dim (2 x 64)
    int b = blockIdx.z;
    int n0 = blockIdx.y * 128, c0 = blockIdx.x * 256;

    const uint16_t* V = g_v + ((size_t)b * C + c0) * NPOS;
    const uint16_t* P = g_P + ((size_t)b * NPOS + n0) * NPOS;

    const int KT = NPOS / 64;
    const int STG = 49152;

    auto load_stage = [&](int s, int kt) {
        int mb = kt * 64;
        uint32_t st = sbase + s * STG;
#pragma unroll
        for (int i = 0; i < 8; i++) {
            int idx = i * 256 + tid;
            int r = idx >> 3, c = idx & 7;
            int cs = c ^ (r & 7);
            cpa16(st + r * 128 + cs * 16, V + (size_t)r * NPOS + mb + c * 8);
        }
#pragma unroll
        for (int i = 0; i < 4; i++) {
            int idx = i * 256 + tid;
            int r = idx >> 3, c = idx & 7;
            int cs = c ^ (r & 7);
            cpa16(st + 32768 + r * 128 + cs * 16, P + (size_t)r * NPOS + mb + c * 8);
        }
        cpcommit();
    };

    load_stage(0, 0);
    load_stage(1, 1);

    float acc[4][8][4];
#pragma unroll
    for (int i = 0; i < 4; i++)
#pragma unroll
        for (int j = 0; j < 8; j++)
#pragma unroll
            for (int k = 0; k < 4; k++) acc[i][j][k] = 0.f;

    int a_row_b = warp_mi * 64 + (lane & 15);
    int a_cadd = lane >> 4;
    int b_row_b = warp_ni * 64 + (lane & 7) + ((lane >> 4) << 3);
    int b_cadd = (lane >> 3) & 1;

    for (int kt = 0; kt < KT; kt++) {
        if (kt >= KT - 1) cpwait<0>(); else cpwait<1>();
        __syncthreads();
        if (kt + 2 < KT) load_stage((kt + 2) % 3, kt + 2);

        uint32_t sA = sbase + (kt % 3) * STG;
        uint32_t sB = sA + 32768;
#pragma unroll
        for (int ks = 0; ks < 4; ks++) {
            int kc = ks * 2;
            uint32_t a[4][4];
#pragma unroll
            for (int mi = 0; mi < 4; mi++) {
                int row = a_row_b + mi * 16;
                int cs = (kc + a_cadd) ^ (row & 7);
                ldm_x4(a[mi], sA + row * 128 + cs * 16);
            }
            uint32_t bf[4][4];
#pragma unroll
            for (int j2 = 0; j2 < 4; j2++) {
                int row = b_row_b + j2 * 16;
                int cs = (kc + b_cadd) ^ (row & 7);
                ldm_x4(bf[j2], sB + row * 128 + cs * 16);
            }
#pragma unroll
            for (int mi = 0; mi < 4; mi++)
#pragma unroll
                for (int ni = 0; ni < 8; ni++)
                    mma_h(acc[mi][ni], a[mi], &bf[ni >> 1][(ni & 1) * 2]);
        }
    }

    int g = lane >> 2, tq = lane & 3;
    float gm = gamma[0];
    float2 iv[8];
#pragma unroll
    for (int ni = 0; ni < 8; ni++) {
        int ncol = n0 + warp_ni * 64 + ni * 8 + 2 * tq;
        float2 sv = *(const float2*)&g_sum[b * NPOS + ncol];
        iv[ni].x = 1.f / sv.x;
        iv[ni].y = 1.f / sv.y;
    }

#pragma unroll
    for (int mi = 0; mi < 4; mi++) {
        int c_r0 = c0 + warp_mi * 64 + mi * 16 + g;
        int c_r1 = c_r0 + 8;
#pragma unroll
        for (int ni = 0; ni < 8; ni++) {
            int ncol = n0 + warp_ni * 64 + ni * 8 + 2 * tq;
            size_t off0 = ((size_t)b * C + c_r0) * NPOS + ncol;
            size_t off1 = ((size_t)b * C + c_r1) * NPOS + ncol;
            float2 xv0 = *(const float2*)&x[off0];
            float2 xv1 = *(const float2*)&x[off1];
            float2 o0, o1;
            o0.x = gm * iv[ni].x * acc[mi][ni][0] + xv0.x;
            o0.y = gm * iv[ni].y * acc[mi][ni][1] + xv0.y;
            o1.x = gm * iv[ni].x * acc[mi][ni][2] + xv1.x;
            o1.y = gm * iv[ni].y * acc[mi][ni][3] + xv1.y;
            *(float2*)&out[off0] = o0;
            *(float2*)&out[off1] = o1;
        }
    }
}

// ---------------------------------------------------------------------------
extern "C" void kernel_launch(void* const* d_in, const int* in_sizes, int n_in,
                              void* d_out, int out_size)
{
    const float* x     = (const float*)d_in[0];
    const float* Wq    = (const float*)d_in[1];
    const float* bq    = (const float*)d_in[2];
    const float* Wk    = (const float*)d_in[3];
    const float* bk    = (const float*)d_in[4];
    const float* Wv    = (const float*)d_in[5];
    const float* bv    = (const float*)d_in[6];
    const float* gamma = (const float*)d_in[7];
    float* out = (float*)d_out;

    cudaFuncSetAttribute(proj_qk_kernel,
                         cudaFuncAttributeMaxDynamicSharedMemorySize, 65536);
    cudaFuncSetAttribute(proj_v_kernel,
                         cudaFuncAttributeMaxDynamicSharedMemorySize, 65536);
    cudaFuncSetAttribute(energy_kernel,
                         cudaFuncAttributeMaxDynamicSharedMemorySize, 49152);
    cudaFuncSetAttribute(out_kernel,
                         cudaFuncAttributeMaxDynamicSharedMemorySize, 147456);

    cvt_x_kernel<<<(int)((size_t)BATCH * C * NPOS / 4 / 256), 256>>>(x);

    proj_qk_kernel<<<dim3(NPOS / 128, 1, BATCH), 256, 65536>>>(Wq, bq, Wk, bk);
    proj_v_kernel<<<dim3(NPOS / 128, C / 128, BATCH), 256, 65536>>>(Wv, bv);

    energy_kernel<<<dim3(NPOS / (128 * MB), NPOS / 128, BATCH), 256, 49152>>>();

    out_kernel<<<dim3(C / 256, NPOS / 128, BATCH), 256, 147456>>>(x, gamma, out);
}

// round 12
// speedup vs baseline: 1.1290x; 1.0617x over previous
#include <cuda_runtime.h>
#include <cstdint>

#define BATCH 4
#define C 512
#define CQ 64
#define NPOS 4096

#define LOG2E 1.4426950408889634f
#define PSHIFT 4.0f
#define MB 4                       // m-tiles per energy CTA

// ---------------- scratch (device globals) ----------------------------------
__device__ uint16_t g_qbT[(size_t)BATCH * NPOS * CQ];   // [b][n][o] f16, pre-scaled log2e
__device__ uint16_t g_kbT[(size_t)BATCH * NPOS * CQ];   // [b][m][o] f16
__device__ uint16_t g_v [(size_t)BATCH * C * NPOS];     // [b][c][m] f16
__device__ uint16_t g_P [(size_t)BATCH * NPOS * NPOS];  // [b][n][m] f16 2^(E'-4)
__device__ uint16_t g_xb[(size_t)BATCH * C * NPOS];     // [b][c][n] f16
__device__ float    g_sum[BATCH * NPOS];

// ---------------- helpers ----------------------------------------------------
__device__ __forceinline__ unsigned smem_u32(const void* p) {
    return (unsigned)__cvta_generic_to_shared(p);
}
__device__ __forceinline__ void cpa16(unsigned s, const void* g) {
    asm volatile("cp.async.cg.shared.global [%0], [%1], 16;\n" :: "r"(s), "l"(g));
}
__device__ __forceinline__ void cpcommit() { asm volatile("cp.async.commit_group;\n" ::); }
template <int n>
__device__ __forceinline__ void cpwait() { asm volatile("cp.async.wait_group %0;\n" :: "n"(n)); }

__device__ __forceinline__ uint32_t hpack(float lo, float hi) {
    uint32_t u;
    asm("cvt.rn.f16x2.f32 %0, %1, %2;" : "=r"(u) : "f"(hi), "f"(lo));
    return u;
}
__device__ __forceinline__ uint16_t h16of(float x) {
    uint16_t h;
    asm("cvt.rn.f16.f32 %0, %1;" : "=h"(h) : "f"(x));
    return h;
}
__device__ __forceinline__ uint32_t ex2h2(uint32_t x) {
    uint32_t d;
    asm("ex2.approx.f16x2 %0, %1;" : "=r"(d) : "r"(x));
    return d;
}
__device__ __forceinline__ void ldm_x4(uint32_t* r, uint32_t addr) {
    asm volatile("ldmatrix.sync.aligned.m8n8.x4.shared.b16 {%0,%1,%2,%3}, [%4];"
        : "=r"(r[0]), "=r"(r[1]), "=r"(r[2]), "=r"(r[3]) : "r"(addr));
}
__device__ __forceinline__ void ldm_x4_t(uint32_t* r, uint32_t addr) {
    asm volatile("ldmatrix.sync.aligned.m8n8.x4.trans.shared.b16 {%0,%1,%2,%3}, [%4];"
        : "=r"(r[0]), "=r"(r[1]), "=r"(r[2]), "=r"(r[3]) : "r"(addr));
}
__device__ __forceinline__ void mma_h(float* d, const uint32_t* a, const uint32_t* b) {
    asm volatile("mma.sync.aligned.m16n8k16.row.col.f32.f16.f16.f32 "
        "{%0,%1,%2,%3}, {%4,%5,%6,%7}, {%8,%9}, {%0,%1,%2,%3};"
        : "+f"(d[0]), "+f"(d[1]), "+f"(d[2]), "+f"(d[3])
        : "r"(a[0]), "r"(a[1]), "r"(a[2]), "r"(a[3]), "r"(b[0]), "r"(b[1]));
}

extern __shared__ __align__(16) char smem[];

// ---------------------------------------------------------------------------
// x (fp32) -> g_xb (f16); first 16384 threads also zero g_sum.
__global__ void cvt_x_kernel(const float* __restrict__ x) {
    int t = blockIdx.x * 256 + threadIdx.x;
    if (t < BATCH * NPOS) g_sum[t] = 0.f;
    size_t i = (size_t)t * 4;
    float4 v = *(const float4*)&x[i];
    uint2 o;
    o.x = hpack(v.x, v.y);
    o.y = hpack(v.z, v.w);
    *(uint2*)&g_xb[i] = o;
}

// ---------------------------------------------------------------------------
// Fused q/k projection (f16 mma). rows 0-63 = Wq (scaled by log2e), 64-127 = Wk.
// Epilogue stores TRANSPOSED f16 [n][o].
// ---------------------------------------------------------------------------
__global__ __launch_bounds__(256) void proj_qk_kernel(
    const float* __restrict__ Wq, const float* __restrict__ bq,
    const float* __restrict__ Wk, const float* __restrict__ bk)
{
    uint32_t sbase = smem_u32(smem);

    int tid = threadIdx.x, lane = tid & 31, wid = tid >> 5;
    int warp_mi = wid >> 2;        // 0 = q rows, 1 = k rows
    int warp_ni = wid & 3;
    int b = blockIdx.z;
    int n0 = blockIdx.x * 128;

    const uint16_t* X = g_xb + (size_t)b * C * NPOS;
    const int KT = C / 64;

    float aw[4][8];
    auto ldgA = [&](int kt) {
#pragma unroll
        for (int i = 0; i < 4; i++) {
            int idx = tid + i * 256;
            int r = idx >> 3, c = idx & 7;
            const float* src = (r < 64)
                ? Wq + (size_t)r * C + kt * 64 + c * 8
                : Wk + (size_t)(r - 64) * C + kt * 64 + c * 8;
            float4 v0 = *(const float4*)src;
            float4 v1 = *(const float4*)(src + 4);
            aw[i][0] = v0.x; aw[i][1] = v0.y; aw[i][2] = v0.z; aw[i][3] = v0.w;
            aw[i][4] = v1.x; aw[i][5] = v1.y; aw[i][6] = v1.z; aw[i][7] = v1.w;
        }
    };
    auto stsA = [&](int s) {
#pragma unroll
        for (int i = 0; i < 4; i++) {
            int idx = tid + i * 256;
            int r = idx >> 3, c = idx & 7;
            int cs = c ^ (r & 7);
            uint4 o;
            o.x = hpack(aw[i][0], aw[i][1]);
            o.y = hpack(aw[i][2], aw[i][3]);
            o.z = hpack(aw[i][4], aw[i][5]);
            o.w = hpack(aw[i][6], aw[i][7]);
            *(uint4*)(smem + s * 32768 + r * 128 + cs * 16) = o;
        }
    };
    auto cpaB = [&](int kt, int s) {
#pragma unroll
        for (int i = 0; i < 4; i++) {
            int idx = tid + i * 256;
            int r = idx >> 4, c = idx & 15;
            int cs = (c & 8) | ((c & 7) ^ (r & 7));
            cpa16(sbase + s * 32768 + 16384 + r * 256 + cs * 16,
                  X + (size_t)(kt * 64 + r) * NPOS + n0 + c * 8);
        }
        cpcommit();
    };

    float acc[4][4][4];
#pragma unroll
    for (int i = 0; i < 4; i++)
#pragma unroll
        for (int j = 0; j < 4; j++)
#pragma unroll
            for (int k = 0; k < 4; k++) acc[i][j][k] = 0.f;

    ldgA(0);
    cpaB(0, 0);
    stsA(0);

    for (int kt = 0; kt < KT; kt++) {
        cpwait<0>();
        __syncthreads();
        if (kt + 1 < KT) {
            cpaB(kt + 1, (kt + 1) & 1);
            ldgA(kt + 1);
        }
        uint32_t sA = sbase + (kt & 1) * 32768;
        uint32_t sB = sA + 16384;
#pragma unroll
        for (int ks = 0; ks < 4; ks++) {
            uint32_t a[4][4];
#pragma unroll
            for (int mi = 0; mi < 4; mi++) {
                int row = warp_mi * 64 + mi * 16 + (lane & 15);
                int ch = ks * 2 + (lane >> 4);
                int cs = ch ^ (row & 7);
                ldm_x4(a[mi], sA + row * 128 + cs * 16);
            }
            uint32_t bf[2][4];
#pragma unroll
            for (int nb = 0; nb < 2; nb++) {
                int krow = ks * 16 + (lane & 7) + ((lane >> 3) & 1) * 8;
                int nch = warp_ni * 4 + nb * 2 + (lane >> 4);
                int cs = (nch & 8) | ((nch & 7) ^ (krow & 7));
                ldm_x4_t(bf[nb], sB + krow * 256 + cs * 16);
            }
#pragma unroll
            for (int mi = 0; mi < 4; mi++)
#pragma unroll
                for (int ni = 0; ni < 4; ni++)
                    mma_h(acc[mi][ni], a[mi], &bf[ni >> 1][(ni & 1) * 2]);
        }
        if (kt + 1 < KT) stsA((kt + 1) & 1);
    }

    int g = lane >> 2, tq = lane & 3;
    uint16_t* Y = (warp_mi == 0 ? g_qbT : g_kbT) + (size_t)b * NPOS * CQ;
    float scale = (warp_mi == 0) ? LOG2E : 1.0f;
#pragma unroll
    for (int mi = 0; mi < 4; mi++) {
        int o0 = mi * 16 + g;
        int o1 = o0 + 8;
        float bv0 = (warp_mi == 0) ? bq[o0] : bk[o0];
        float bv1 = (warp_mi == 0) ? bq[o1] : bk[o1];
#pragma unroll
        for (int ni = 0; ni < 4; ni++) {
            int ncol = n0 + warp_ni * 32 + ni * 8 + 2 * tq;
            Y[(size_t)ncol * CQ + o0]       = h16of((acc[mi][ni][0] + bv0) * scale);
            Y[(size_t)(ncol + 1) * CQ + o0] = h16of((acc[mi][ni][1] + bv0) * scale);
            Y[(size_t)ncol * CQ + o1]       = h16of((acc[mi][ni][2] + bv1) * scale);
            Y[(size_t)(ncol + 1) * CQ + o1] = h16of((acc[mi][ni][3] + bv1) * scale);
        }
    }
}

// ---------------------------------------------------------------------------
// proj_v (f16 mma): V[c][n] = sum_k Wv[c][k]*xb[k][n] + bv[c], store f16.
// ---------------------------------------------------------------------------
__global__ __launch_bounds__(256) void proj_v_kernel(
    const float* __restrict__ W, const float* __restrict__ bias)
{
    uint32_t sbase = smem_u32(smem);

    int tid = threadIdx.x, lane = tid & 31, wid = tid >> 5;
    int warp_mi = wid >> 2;
    int warp_ni = wid & 3;
    int b = blockIdx.z;
    int n0 = blockIdx.x * 128, c0 = blockIdx.y * 128;

    const uint16_t* X = g_xb + (size_t)b * C * NPOS;
    const int KT = C / 64;

    float aw[4][8];
    auto ldgA = [&](int kt) {
#pragma unroll
        for (int i = 0; i < 4; i++) {
            int idx = tid + i * 256;
            int r = idx >> 3, c = idx & 7;
            const float* src = W + (size_t)(c0 + r) * C + kt * 64 + c * 8;
            float4 v0 = *(const float4*)src;
            float4 v1 = *(const float4*)(src + 4);
            aw[i][0] = v0.x; aw[i][1] = v0.y; aw[i][2] = v0.z; aw[i][3] = v0.w;
            aw[i][4] = v1.x; aw[i][5] = v1.y; aw[i][6] = v1.z; aw[i][7] = v1.w;
        }
    };
    auto stsA = [&](int s) {
#pragma unroll
        for (int i = 0; i < 4; i++) {
            int idx = tid + i * 256;
            int r = idx >> 3, c = idx & 7;
            int cs = c ^ (r & 7);
            uint4 o;
            o.x = hpack(aw[i][0], aw[i][1]);
            o.y = hpack(aw[i][2], aw[i][3]);
            o.z = hpack(aw[i][4], aw[i][5]);
            o.w = hpack(aw[i][6], aw[i][7]);
            *(uint4*)(smem + s * 32768 + r * 128 + cs * 16) = o;
        }
    };
    auto cpaB = [&](int kt, int s) {
#pragma unroll
        for (int i = 0; i < 4; i++) {
            int idx = tid + i * 256;
            int r = idx >> 4, c = idx & 15;
            int cs = (c & 8) | ((c & 7) ^ (r & 7));
            cpa16(sbase + s * 32768 + 16384 + r * 256 + cs * 16,
                  X + (size_t)(kt * 64 + r) * NPOS + n0 + c * 8);
        }
        cpcommit();
    };

    float acc[4][4][4];
#pragma unroll
    for (int i = 0; i < 4; i++)
#pragma unroll
        for (int j = 0; j < 4; j++)
#pragma unroll
            for (int k = 0; k < 4; k++) acc[i][j][k] = 0.f;

    ldgA(0);
    cpaB(0, 0);
    stsA(0);

    for (int kt = 0; kt < KT; kt++) {
        cpwait<0>();
        __syncthreads();
        if (kt + 1 < KT) {
            cpaB(kt + 1, (kt + 1) & 1);
            ldgA(kt + 1);
        }
        uint32_t sA = sbase + (kt & 1) * 32768;
        uint32_t sB = sA + 16384;
#pragma unroll
        for (int ks = 0; ks < 4; ks++) {
            uint32_t a[4][4];
#pragma unroll
            for (int mi = 0; mi < 4; mi++) {
                int row = warp_mi * 64 + mi * 16 + (lane & 15);
                int ch = ks * 2 + (lane >> 4);
                int cs = ch ^ (row & 7);
                ldm_x4(a[mi], sA + row * 128 + cs * 16);
            }
            uint32_t bf[2][4];
#pragma unroll
            for (int nb = 0; nb < 2; nb++) {
                int krow = ks * 16 + (lane & 7) + ((lane >> 3) & 1) * 8;
                int nch = warp_ni * 4 + nb * 2 + (lane >> 4);
                int cs = (nch & 8) | ((nch & 7) ^ (krow & 7));
                ldm_x4_t(bf[nb], sB + krow * 256 + cs * 16);
            }
#pragma unroll
            for (int mi = 0; mi < 4; mi++)
#pragma unroll
                for (int ni = 0; ni < 4; ni++)
                    mma_h(acc[mi][ni], a[mi], &bf[ni >> 1][(ni & 1) * 2]);
        }
        if (kt + 1 < KT) stsA((kt + 1) & 1);
    }

    int g = lane >> 2, tq = lane & 3;
    uint16_t* Vout = g_v + (size_t)b * C * NPOS;
#pragma unroll
    for (int mi = 0; mi < 4; mi++) {
        int c_r0 = c0 + warp_mi * 64 + mi * 16 + g;
        int c_r1 = c_r0 + 8;
        float bv0 = bias[c_r0], bv1 = bias[c_r1];
#pragma unroll
        for (int ni = 0; ni < 4; ni++) {
            int ncol = n0 + warp_ni * 32 + ni * 8 + 2 * tq;
            *(uint32_t*)&Vout[(size_t)c_r0 * NPOS + ncol] =
                hpack(acc[mi][ni][0] + bv0, acc[mi][ni][1] + bv0);
            *(uint32_t*)&Vout[(size_t)c_r1 * NPOS + ncol] =
                hpack(acc[mi][ni][2] + bv1, acc[mi][ni][3] + bv1);
        }
    }
}

// ---------------------------------------------------------------------------
// Energy (f16 mma, persistent m-loop): q-tile resident, MB=4 key-tiles with
// double-buffered B loads; P = 2^(acc-4) via ex2.f16x2; row-sum mma-with-ones
// accumulated; one atomicAdd per row at the end.
// ---------------------------------------------------------------------------
__global__ __launch_bounds__(256) void energy_kernel()
{
    uint32_t sA = smem_u32(smem);
    uint32_t sB0 = sA + 16384;

    int tid = threadIdx.x, lane = tid & 31, wid = tid >> 5;
    int warp_mi = wid >> 2;        // n-dim (2 x 64)
    int warp_ni = wid & 3;         // m-dim (4 x 32)
    int b = blockIdx.z;
    int n0 = blockIdx.y * 128;
    int mbase = blockIdx.x * (MB * 128);

    const uint16_t* Aq = g_qbT + ((size_t)b * NPOS + n0) * CQ;
    const uint16_t* Bk = g_kbT + (size_t)b * NPOS * CQ;

    auto cpaB = [&](int m0, uint32_t dst) {
#pragma unroll
        for (int i = 0; i < 4; i++) {
            int idx = i * 256 + tid;
            int r = idx >> 3, c = idx & 7;
            int cs = c ^ (r & 7);
            cpa16(dst + r * 128 + cs * 16, Bk + (size_t)(m0 + r) * CQ + c * 8);
        }
        cpcommit();
    };

#pragma unroll
    for (int i = 0; i < 4; i++) {
        int idx = i * 256 + tid;
        int r = idx >> 3, c = idx & 7;
        int cs = c ^ (r & 7);
        cpa16(sA + r * 128 + cs * 16, Aq + (size_t)r * CQ + c * 8);
    }
    cpaB(mbase, sB0);

    int a_row_b = warp_mi * 64 + (lane & 15);
    int a_cadd = lane >> 4;
    int b_row_b = warp_ni * 32 + (lane & 7) + ((lane >> 4) << 3);
    int b_cadd = (lane >> 3) & 1;
    int g = lane >> 2, tq = lane & 3;

    uint16_t* Pout = g_P + (size_t)b * NPOS * NPOS;
    uint32_t onesb[2] = {0x3C003C00u, 0x3C003C00u};
    float ssum[4][4];
#pragma unroll
    for (int i = 0; i < 4; i++)
#pragma unroll
        for (int k = 0; k < 4; k++) ssum[i][k] = 0.f;

    for (int mt = 0; mt < MB; mt++) {
        int m0 = mbase + mt * 128;
        uint32_t sB = sB0 + (mt & 1) * 16384;

        cpwait<0>();
        __syncthreads();
        if (mt + 1 < MB)
            cpaB(m0 + 128, sB0 + ((mt + 1) & 1) * 16384);

        float acc[4][4][4];
#pragma unroll
        for (int i = 0; i < 4; i++)
#pragma unroll
            for (int j = 0; j < 4; j++)
#pragma unroll
                for (int k = 0; k < 4; k++) acc[i][j][k] = 0.f;

#pragma unroll
        for (int ks = 0; ks < 4; ks++) {
            int kc = ks * 2;
            uint32_t a[4][4];
#pragma unroll
            for (int mi = 0; mi < 4; mi++) {
                int row = a_row_b + mi * 16;
                int cs = (kc + a_cadd) ^ (row & 7);
                ldm_x4(a[mi], sA + row * 128 + cs * 16);
            }
            uint32_t bf[2][4];
#pragma unroll
            for (int j2 = 0; j2 < 2; j2++) {
                int row = b_row_b + j2 * 16;
                int cs = (kc + b_cadd) ^ (row & 7);
                ldm_x4(bf[j2], sB + row * 128 + cs * 16);
            }
#pragma unroll
            for (int mi = 0; mi < 4; mi++)
#pragma unroll
                for (int ni = 0; ni < 4; ni++)
                    mma_h(acc[mi][ni], a[mi], &bf[ni >> 1][(ni & 1) * 2]);
        }

#pragma unroll
        for (int mi = 0; mi < 4; mi++) {
            int r0 = n0 + warp_mi * 64 + mi * 16 + g;
            int r1 = r0 + 8;
            uint32_t e01[4], e23[4];
#pragma unroll
            for (int ni = 0; ni < 4; ni++) {
                e01[ni] = ex2h2(hpack(acc[mi][ni][0] - PSHIFT, acc[mi][ni][1] - PSHIFT));
                e23[ni] = ex2h2(hpack(acc[mi][ni][2] - PSHIFT, acc[mi][ni][3] - PSHIFT));
                int col = m0 + warp_ni * 32 + ni * 8 + 2 * tq;
                *(uint32_t*)&Pout[(size_t)r0 * NPOS + col] = e01[ni];
                *(uint32_t*)&Pout[(size_t)r1 * NPOS + col] = e23[ni];
            }
            uint32_t A0[4] = {e01[0], e23[0], e01[1], e23[1]};
            uint32_t A1[4] = {e01[2], e23[2], e01[3], e23[3]};
            mma_h(ssum[mi], A0, onesb);
            mma_h(ssum[mi], A1, onesb);
        }
        __syncthreads();
    }

    if (tq == 0) {
        float* SUM = g_sum + b * NPOS;
#pragma unroll
        for (int mi = 0; mi < 4; mi++) {
            int r0 = n0 + warp_mi * 64 + mi * 16 + g;
            atomicAdd(&SUM[r0], ssum[mi][0]);
            atomicAdd(&SUM[r0 + 8], ssum[mi][2]);
        }
    }
}

// ---------------------------------------------------------------------------
// Out (f16 mma, 128x128 tile, 3-stage, 2 CTAs/SM): D[c][n] = sum_m V[c][m]*P[n][m]
// Epilogue: out = gamma*(1/sum[n])*D + x. blockIdx.x = c-block (P L2 reuse).
// smem: 3 x 32KB = 96KB -> 2 CTAs/SM; __launch_bounds__(256,2) caps regs at 128.
// ---------------------------------------------------------------------------
__global__ __launch_bounds__(256, 2) void out_kernel(
    const float* __restrict__ x, const float* __restrict__ gamma,
    float* __restrict__ out)
{
    uint32_t sbase = smem_u32(smem);

    int tid = threadIdx.x, lane = tid & 31, wid = tid >> 5;
    int warp_mi = wid >> 2;        // c-dim (2 x 64)
    int warp_ni = wid & 3;         // n-dim (4 x 32)
    int b = blockIdx.z;
    int n0 = blockIdx.y * 128, c0 = blockIdx.x * 128;

    const uint16_t* V = g_v + ((size_t)b * C + c0) * NPOS;
    const uint16_t* P = g_P + ((size_t)b * NPOS + n0) * NPOS;

    const int KT = NPOS / 64;      // 64
    const int STG = 32768;         // 16KB A + 16KB B per stage

    auto load_stage = [&](int s, int kt) {
        int mb = kt * 64;
        uint32_t st = sbase + s * STG;
#pragma unroll
        for (int i = 0; i < 4; i++) {
            int idx = i * 256 + tid;
            int r = idx >> 3, c = idx & 7;
            int cs = c ^ (r & 7);
            cpa16(st + r * 128 + cs * 16, V + (size_t)r * NPOS + mb + c * 8);
            cpa16(st + 16384 + r * 128 + cs * 16, P + (size_t)r * NPOS + mb + c * 8);
        }
        cpcommit();
    };

    load_stage(0, 0);
    load_stage(1, 1);

    float acc[4][4][4];
#pragma unroll
    for (int i = 0; i < 4; i++)
#pragma unroll
        for (int j = 0; j < 4; j++)
#pragma unroll
            for (int k = 0; k < 4; k++) acc[i][j][k] = 0.f;

    int a_row_b = warp_mi * 64 + (lane & 15);
    int a_cadd = lane >> 4;
    int b_row_b = warp_ni * 32 + (lane & 7) + ((lane >> 4) << 3);
    int b_cadd = (lane >> 3) & 1;

    for (int kt = 0; kt < KT; kt++) {
        if (kt >= KT - 1) cpwait<0>(); else cpwait<1>();
        __syncthreads();
        if (kt + 2 < KT) load_stage((kt + 2) % 3, kt + 2);

        uint32_t sA = sbase + (kt % 3) * STG;
        uint32_t sB = sA + 16384;
#pragma unroll
        for (int ks = 0; ks < 4; ks++) {
            int kc = ks * 2;
            uint32_t a[4][4];
#pragma unroll
            for (int mi = 0; mi < 4; mi++) {
                int row = a_row_b + mi * 16;
                int cs = (kc + a_cadd) ^ (row & 7);
                ldm_x4(a[mi], sA + row * 128 + cs * 16);
            }
            uint32_t bf[2][4];
#pragma unroll
            for (int j2 = 0; j2 < 2; j2++) {
                int row = b_row_b + j2 * 16;
                int cs = (kc + b_cadd) ^ (row & 7);
                ldm_x4(bf[j2], sB + row * 128 + cs * 16);
            }
#pragma unroll
            for (int mi = 0; mi < 4; mi++)
#pragma unroll
                for (int ni = 0; ni < 4; ni++)
                    mma_h(acc[mi][ni], a[mi], &bf[ni >> 1][(ni & 1) * 2]);
        }
    }

    int g = lane >> 2, tq = lane & 3;
    float gm = gamma[0];
    float2 iv[4];
#pragma unroll
    for (int ni = 0; ni < 4; ni++) {
        int ncol = n0 + warp_ni * 32 + ni * 8 + 2 * tq;
        float2 sv = *(const float2*)&g_sum[b * NPOS + ncol];
        iv[ni].x = 1.f / sv.x;
        iv[ni].y = 1.f / sv.y;
    }

#pragma unroll
    for (int mi = 0; mi < 4; mi++) {
        int c_r0 = c0 + warp_mi * 64 + mi * 16 + g;
        int c_r1 = c_r0 + 8;
#pragma unroll
        for (int ni = 0; ni < 4; ni++) {
            int ncol = n0 + warp_ni * 32 + ni * 8 + 2 * tq;
            size_t off0 = ((size_t)b * C + c_r0) * NPOS + ncol;
            size_t off1 = ((size_t)b * C + c_r1) * NPOS + ncol;
            float2 xv0 = *(const float2*)&x[off0];
            float2 xv1 = *(const float2*)&x[off1];
            float2 o0, o1;
            o0.x = gm * iv[ni].x * acc[mi][ni][0] + xv0.x;
            o0.y = gm * iv[ni].y * acc[mi][ni][1] + xv0.y;
            o1.x = gm * iv[ni].x * acc[mi][ni][2] + xv1.x;
            o1.y = gm * iv[ni].y * acc[mi][ni][3] + xv1.y;
            *(float2*)&out[off0] = o0;
            *(float2*)&out[off1] = o1;
        }
    }
}

// ---------------------------------------------------------------------------
extern "C" void kernel_launch(void* const* d_in, const int* in_sizes, int n_in,
                              void* d_out, int out_size)
{
    const float* x     = (const float*)d_in[0];
    const float* Wq    = (const float*)d_in[1];
    const float* bq    = (const float*)d_in[2];
    const float* Wk    = (const float*)d_in[3];
    const float* bk    = (const float*)d_in[4];
    const float* Wv    = (const float*)d_in[5];
    const float* bv    = (const float*)d_in[6];
    const float* gamma = (const float*)d_in[7];
    float* out = (float*)d_out;

    cudaFuncSetAttribute(proj_qk_kernel,
                         cudaFuncAttributeMaxDynamicSharedMemorySize, 65536);
    cudaFuncSetAttribute(proj_v_kernel,
                         cudaFuncAttributeMaxDynamicSharedMemorySize, 65536);
    cudaFuncSetAttribute(energy_kernel,
                         cudaFuncAttributeMaxDynamicSharedMemorySize, 49152);
    cudaFuncSetAttribute(out_kernel,
                         cudaFuncAttributeMaxDynamicSharedMemorySize, 98304);

    cvt_x_kernel<<<(int)((size_t)BATCH * C * NPOS / 4 / 256), 256>>>(x);

    proj_qk_kernel<<<dim3(NPOS / 128, 1, BATCH), 256, 65536>>>(Wq, bq, Wk, bk);
    proj_v_kernel<<<dim3(NPOS / 128, C / 128, BATCH), 256, 65536>>>(Wv, bv);

    energy_kernel<<<dim3(NPOS / (128 * MB), NPOS / 128, BATCH), 256, 49152>>>();

    out_kernel<<<dim3(C / 128, NPOS / 128, BATCH), 256, 98304>>>(x, gamma, out);
}

// round 14
// speedup vs baseline: 1.1897x; 1.0537x over previous
#include <cuda_runtime.h>
#include <cstdint>

#define BATCH 4
#define C 512
#define CQ 64
#define NPOS 4096

#define LOG2E 1.4426950408889634f
#define PSHIFT 4.0f
#define MB 4                       // m-tiles per energy CTA

// ---------------- scratch (device globals) ----------------------------------
__device__ uint16_t g_qbT[(size_t)BATCH * NPOS * CQ];   // [b][n][o] f16, pre-scaled log2e
__device__ uint16_t g_kbT[(size_t)BATCH * NPOS * CQ];   // [b][m][o] f16
__device__ uint16_t g_v [(size_t)BATCH * C * NPOS];     // [b][c][m] f16
__device__ uint16_t g_P [(size_t)BATCH * NPOS * NPOS];  // [b][n][m] f16 2^(E'-4)
__device__ uint16_t g_xb[(size_t)BATCH * C * NPOS];     // [b][c][n] f16
__device__ float    g_sum[BATCH * NPOS];

// ---------------- helpers ----------------------------------------------------
__device__ __forceinline__ unsigned smem_u32(const void* p) {
    return (unsigned)__cvta_generic_to_shared(p);
}
__device__ __forceinline__ void cpa16(unsigned s, const void* g) {
    asm volatile("cp.async.cg.shared.global [%0], [%1], 16;\n" :: "r"(s), "l"(g));
}
__device__ __forceinline__ void cpcommit() { asm volatile("cp.async.commit_group;\n" ::); }
template <int n>
__device__ __forceinline__ void cpwait() { asm volatile("cp.async.wait_group %0;\n" :: "n"(n)); }

__device__ __forceinline__ uint32_t hpack(float lo, float hi) {
    uint32_t u;
    asm("cvt.rn.f16x2.f32 %0, %1, %2;" : "=r"(u) : "f"(hi), "f"(lo));
    return u;
}
__device__ __forceinline__ uint16_t h16of(float x) {
    uint16_t h;
    asm("cvt.rn.f16.f32 %0, %1;" : "=h"(h) : "f"(x));
    return h;
}
__device__ __forceinline__ uint32_t ex2h2(uint32_t x) {
    uint32_t d;
    asm("ex2.approx.f16x2 %0, %1;" : "=r"(d) : "r"(x));
    return d;
}
__device__ __forceinline__ void ldm_x4(uint32_t* r, uint32_t addr) {
    asm volatile("ldmatrix.sync.aligned.m8n8.x4.shared.b16 {%0,%1,%2,%3}, [%4];"
        : "=r"(r[0]), "=r"(r[1]), "=r"(r[2]), "=r"(r[3]) : "r"(addr));
}
__device__ __forceinline__ void ldm_x4_t(uint32_t* r, uint32_t addr) {
    asm volatile("ldmatrix.sync.aligned.m8n8.x4.trans.shared.b16 {%0,%1,%2,%3}, [%4];"
        : "=r"(r[0]), "=r"(r[1]), "=r"(r[2]), "=r"(r[3]) : "r"(addr));
}
__device__ __forceinline__ void mma_h(float* d, const uint32_t* a, const uint32_t* b) {
    asm volatile("mma.sync.aligned.m16n8k16.row.col.f32.f16.f16.f32 "
        "{%0,%1,%2,%3}, {%4,%5,%6,%7}, {%8,%9}, {%0,%1,%2,%3};"
        : "+f"(d[0]), "+f"(d[1]), "+f"(d[2]), "+f"(d[3])
        : "r"(a[0]), "r"(a[1]), "r"(a[2]), "r"(a[3]), "r"(b[0]), "r"(b[1]));
}

extern __shared__ __align__(16) char smem[];

// ---------------------------------------------------------------------------
// x (fp32) -> g_xb (f16); first 16384 threads also zero g_sum.
__global__ void cvt_x_kernel(const float* __restrict__ x) {
    int t = blockIdx.x * 256 + threadIdx.x;
    if (t < BATCH * NPOS) g_sum[t] = 0.f;
    size_t i = (size_t)t * 4;
    float4 v = *(const float4*)&x[i];
    uint2 o;
    o.x = hpack(v.x, v.y);
    o.y = hpack(v.z, v.w);
    *(uint2*)&g_xb[i] = o;
}

// ---------------------------------------------------------------------------
// Merged projection kernel (f16 mma). blockIdx.y selects work:
//   y = 0..3 : V rows c0 = y*128 from Wv -> g_v f16 [c][n]
//   y = 4    : rows 0-63 = Wq (scaled log2e at store), 64-127 = Wk
//              -> transposed stores g_qbT/g_kbT [n][o]
// ---------------------------------------------------------------------------
__global__ __launch_bounds__(256) void proj_all_kernel(
    const float* __restrict__ Wv, const float* __restrict__ bv,
    const float* __restrict__ Wq, const float* __restrict__ bq,
    const float* __restrict__ Wk, const float* __restrict__ bk)
{
    uint32_t sbase = smem_u32(smem);

    int tid = threadIdx.x, lane = tid & 31, wid = tid >> 5;
    int warp_mi = wid >> 2;
    int warp_ni = wid & 3;
    int b = blockIdx.z;
    int n0 = blockIdx.x * 128;
    int yb = blockIdx.y;           // 0..3 = V c-blocks, 4 = qk
    bool is_qk = (yb == 4);
    int c0 = yb * 128;

    const uint16_t* X = g_xb + (size_t)b * C * NPOS;
    const int KT = C / 64;

    float aw[4][8];
    auto ldgA = [&](int kt) {
#pragma unroll
        for (int i = 0; i < 4; i++) {
            int idx = tid + i * 256;
            int r = idx >> 3, c = idx & 7;
            const float* src;
            if (is_qk)
                src = (r < 64) ? Wq + (size_t)r * C + kt * 64 + c * 8
                               : Wk + (size_t)(r - 64) * C + kt * 64 + c * 8;
            else
                src = Wv + (size_t)(c0 + r) * C + kt * 64 + c * 8;
            float4 v0 = *(const float4*)src;
            float4 v1 = *(const float4*)(src + 4);
            aw[i][0] = v0.x; aw[i][1] = v0.y; aw[i][2] = v0.z; aw[i][3] = v0.w;
            aw[i][4] = v1.x; aw[i][5] = v1.y; aw[i][6] = v1.z; aw[i][7] = v1.w;
        }
    };
    auto stsA = [&](int s) {
#pragma unroll
        for (int i = 0; i < 4; i++) {
            int idx = tid + i * 256;
            int r = idx >> 3, c = idx & 7;
            int cs = c ^ (r & 7);
            uint4 o;
            o.x = hpack(aw[i][0], aw[i][1]);
            o.y = hpack(aw[i][2], aw[i][3]);
            o.z = hpack(aw[i][4], aw[i][5]);
            o.w = hpack(aw[i][6], aw[i][7]);
            *(uint4*)(smem + s * 32768 + r * 128 + cs * 16) = o;
        }
    };
    auto cpaB = [&](int kt, int s) {
#pragma unroll
        for (int i = 0; i < 4; i++) {
            int idx = tid + i * 256;
            int r = idx >> 4, c = idx & 15;
            int cs = (c & 8) | ((c & 7) ^ (r & 7));
            cpa16(sbase + s * 32768 + 16384 + r * 256 + cs * 16,
                  X + (size_t)(kt * 64 + r) * NPOS + n0 + c * 8);
        }
        cpcommit();
    };

    float acc[4][4][4];
#pragma unroll
    for (int i = 0; i < 4; i++)
#pragma unroll
        for (int j = 0; j < 4; j++)
#pragma unroll
            for (int k = 0; k < 4; k++) acc[i][j][k] = 0.f;

    ldgA(0);
    cpaB(0, 0);
    stsA(0);

    for (int kt = 0; kt < KT; kt++) {
        cpwait<0>();
        __syncthreads();
        if (kt + 1 < KT) {
            cpaB(kt + 1, (kt + 1) & 1);
            ldgA(kt + 1);
        }
        uint32_t sA = sbase + (kt & 1) * 32768;
        uint32_t sB = sA + 16384;
#pragma unroll
        for (int ks = 0; ks < 4; ks++) {
            uint32_t a[4][4];
#pragma unroll
            for (int mi = 0; mi < 4; mi++) {
                int row = warp_mi * 64 + mi * 16 + (lane & 15);
                int ch = ks * 2 + (lane >> 4);
                int cs = ch ^ (row & 7);
                ldm_x4(a[mi], sA + row * 128 + cs * 16);
            }
            uint32_t bf[2][4];
#pragma unroll
            for (int nb = 0; nb < 2; nb++) {
                int krow = ks * 16 + (lane & 7) + ((lane >> 3) & 1) * 8;
                int nch = warp_ni * 4 + nb * 2 + (lane >> 4);
                int cs = (nch & 8) | ((nch & 7) ^ (krow & 7));
                ldm_x4_t(bf[nb], sB + krow * 256 + cs * 16);
            }
#pragma unroll
            for (int mi = 0; mi < 4; mi++)
#pragma unroll
                for (int ni = 0; ni < 4; ni++)
                    mma_h(acc[mi][ni], a[mi], &bf[ni >> 1][(ni & 1) * 2]);
        }
        if (kt + 1 < KT) stsA((kt + 1) & 1);
    }

    int g = lane >> 2, tq = lane & 3;
    if (is_qk) {
        // transposed f16 stores; warp_mi 0 -> q (scaled), 1 -> k
        uint16_t* Y = (warp_mi == 0 ? g_qbT : g_kbT) + (size_t)b * NPOS * CQ;
        float scale = (warp_mi == 0) ? LOG2E : 1.0f;
#pragma unroll
        for (int mi = 0; mi < 4; mi++) {
            int o0 = mi * 16 + g;
            int o1 = o0 + 8;
            float bv0 = (warp_mi == 0) ? bq[o0] : bk[o0];
            float bv1 = (warp_mi == 0) ? bq[o1] : bk[o1];
#pragma unroll
            for (int ni = 0; ni < 4; ni++) {
                int ncol = n0 + warp_ni * 32 + ni * 8 + 2 * tq;
                Y[(size_t)ncol * CQ + o0]       = h16of((acc[mi][ni][0] + bv0) * scale);
                Y[(size_t)(ncol + 1) * CQ + o0] = h16of((acc[mi][ni][1] + bv0) * scale);
                Y[(size_t)ncol * CQ + o1]       = h16of((acc[mi][ni][2] + bv1) * scale);
                Y[(size_t)(ncol + 1) * CQ + o1] = h16of((acc[mi][ni][3] + bv1) * scale);
            }
        }
    } else {
        uint16_t* Vout = g_v + (size_t)b * C * NPOS;
#pragma unroll
        for (int mi = 0; mi < 4; mi++) {
            int c_r0 = c0 + warp_mi * 64 + mi * 16 + g;
            int c_r1 = c_r0 + 8;
            float bv0 = bv[c_r0], bv1 = bv[c_r1];
#pragma unroll
            for (int ni = 0; ni < 4; ni++) {
                int ncol = n0 + warp_ni * 32 + ni * 8 + 2 * tq;
                *(uint32_t*)&Vout[(size_t)c_r0 * NPOS + ncol] =
                    hpack(acc[mi][ni][0] + bv0, acc[mi][ni][1] + bv0);
                *(uint32_t*)&Vout[(size_t)c_r1 * NPOS + ncol] =
                    hpack(acc[mi][ni][2] + bv1, acc[mi][ni][3] + bv1);
            }
        }
    }
}

// ---------------------------------------------------------------------------
// Energy (f16 mma, persistent m-loop, 2 CTAs/SM): q-tile resident, MB=4
// key-tiles double-buffered; P = 2^(acc-4) via ex2.f16x2; row-sum
// mma-with-ones accumulated; one atomicAdd per row at the end.
// smem 48KB -> 2 CTAs; reg cap 128 via launch bounds.
// ---------------------------------------------------------------------------
__global__ __launch_bounds__(256, 2) void energy_kernel()
{
    uint32_t sA = smem_u32(smem);
    uint32_t sB0 = sA + 16384;

    int tid = threadIdx.x, lane = tid & 31, wid = tid >> 5;
    int warp_mi = wid >> 2;        // n-dim (2 x 64)
    int warp_ni = wid & 3;         // m-dim (4 x 32)
    int b = blockIdx.z;
    int n0 = blockIdx.y * 128;
    int mbase = blockIdx.x * (MB * 128);

    const uint16_t* Aq = g_qbT + ((size_t)b * NPOS + n0) * CQ;
    const uint16_t* Bk = g_kbT + (size_t)b * NPOS * CQ;

    auto cpaB = [&](int m0, uint32_t dst) {
#pragma unroll
        for (int i = 0; i < 4; i++) {
            int idx = i * 256 + tid;
            int r = idx >> 3, c = idx & 7;
            int cs = c ^ (r & 7);
            cpa16(dst + r * 128 + cs * 16, Bk + (size_t)(m0 + r) * CQ + c * 8);
        }
        cpcommit();
    };

#pragma unroll
    for (int i = 0; i < 4; i++) {
        int idx = i * 256 + tid;
        int r = idx >> 3, c = idx & 7;
        int cs = c ^ (r & 7);
        cpa16(sA + r * 128 + cs * 16, Aq + (size_t)r * CQ + c * 8);
    }
    cpaB(mbase, sB0);

    int a_row_b = warp_mi * 64 + (lane & 15);
    int a_cadd = lane >> 4;
    int b_row_b = warp_ni * 32 + (lane & 7) + ((lane >> 4) << 3);
    int b_cadd = (lane >> 3) & 1;
    int g = lane >> 2, tq = lane & 3;

    uint16_t* Pout = g_P + (size_t)b * NPOS * NPOS;
    uint32_t onesb[2] = {0x3C003C00u, 0x3C003C00u};
    float ssum[4][4];
#pragma unroll
    for (int i = 0; i < 4; i++)
#pragma unroll
        for (int k = 0; k < 4; k++) ssum[i][k] = 0.f;

    for (int mt = 0; mt < MB; mt++) {
        int m0 = mbase + mt * 128;
        uint32_t sB = sB0 + (mt & 1) * 16384;

        cpwait<0>();
        __syncthreads();
        if (mt + 1 < MB)
            cpaB(m0 + 128, sB0 + ((mt + 1) & 1) * 16384);

        float acc[4][4][4];
#pragma unroll
        for (int i = 0; i < 4; i++)
#pragma unroll
            for (int j = 0; j < 4; j++)
#pragma unroll
                for (int k = 0; k < 4; k++) acc[i][j][k] = 0.f;

#pragma unroll
        for (int ks = 0; ks < 4; ks++) {
            int kc = ks * 2;
            uint32_t a[4][4];
#pragma unroll
            for (int mi = 0; mi < 4; mi++) {
                int row = a_row_b + mi * 16;
                int cs = (kc + a_cadd) ^ (row & 7);
                ldm_x4(a[mi], sA + row * 128 + cs * 16);
            }
            uint32_t bf[2][4];
#pragma unroll
            for (int j2 = 0; j2 < 2; j2++) {
                int row = b_row_b + j2 * 16;
                int cs = (kc + b_cadd) ^ (row & 7);
                ldm_x4(bf[j2], sB + row * 128 + cs * 16);
            }
#pragma unroll
            for (int mi = 0; mi < 4; mi++)
#pragma unroll
                for (int ni = 0; ni < 4; ni++)
                    mma_h(acc[mi][ni], a[mi], &bf[ni >> 1][(ni & 1) * 2]);
        }

#pragma unroll
        for (int mi = 0; mi < 4; mi++) {
            int r0 = n0 + warp_mi * 64 + mi * 16 + g;
            int r1 = r0 + 8;
            uint32_t e01[4], e23[4];
#pragma unroll
            for (int ni = 0; ni < 4; ni++) {
                e01[ni] = ex2h2(hpack(acc[mi][ni][0] - PSHIFT, acc[mi][ni][1] - PSHIFT));
                e23[ni] = ex2h2(hpack(acc[mi][ni][2] - PSHIFT, acc[mi][ni][3] - PSHIFT));
                int col = m0 + warp_ni * 32 + ni * 8 + 2 * tq;
                *(uint32_t*)&Pout[(size_t)r0 * NPOS + col] = e01[ni];
                *(uint32_t*)&Pout[(size_t)r1 * NPOS + col] = e23[ni];
            }
            uint32_t A0[4] = {e01[0], e23[0], e01[1], e23[1]};
            uint32_t A1[4] = {e01[2], e23[2], e01[3], e23[3]};
            mma_h(ssum[mi], A0, onesb);
            mma_h(ssum[mi], A1, onesb);
        }
        __syncthreads();
    }

    if (tq == 0) {
        float* SUM = g_sum + b * NPOS;
#pragma unroll
        for (int mi = 0; mi < 4; mi++) {
            int r0 = n0 + warp_mi * 64 + mi * 16 + g;
            atomicAdd(&SUM[r0], ssum[mi][0]);
            atomicAdd(&SUM[r0 + 8], ssum[mi][2]);
        }
    }
}

// ---------------------------------------------------------------------------
// Out (f16 mma, 128x128 tile, 3-stage, 2 CTAs/SM): D[c][n] = sum_m V[c][m]*P[n][m]
// Epilogue: out = gamma*(1/sum[n])*D + x. blockIdx.x = c-block (P L2 reuse).
// ---------------------------------------------------------------------------
__global__ __launch_bounds__(256, 2) void out_kernel(
    const float* __restrict__ x, const float* __restrict__ gamma,
    float* __restrict__ out)
{
    uint32_t sbase = smem_u32(smem);

    int tid = threadIdx.x, lane = tid & 31, wid = tid >> 5;
    int warp_mi = wid >> 2;        // c-dim (2 x 64)
    int warp_ni = wid & 3;         // n-dim (4 x 32)
    int b = blockIdx.z;
    int n0 = blockIdx.y * 128, c0 = blockIdx.x * 128;

    const uint16_t* V = g_v + ((size_t)b * C + c0) * NPOS;
    const uint16_t* P = g_P + ((size_t)b * NPOS + n0) * NPOS;

    const int KT = NPOS / 64;      // 64
    const int STG = 32768;         // 16KB A + 16KB B per stage

    auto load_stage = [&](int s, int kt) {
        int mb = kt * 64;
        uint32_t st = sbase + s * STG;
#pragma unroll
        for (int i = 0; i < 4; i++) {
            int idx = i * 256 + tid;
            int r = idx >> 3, c = idx & 7;
            int cs = c ^ (r & 7);
            cpa16(st + r * 128 + cs * 16, V + (size_t)r * NPOS + mb + c * 8);
            cpa16(st + 16384 + r * 128 + cs * 16, P + (size_t)r * NPOS + mb + c * 8);
        }
        cpcommit();
    };

    load_stage(0, 0);
    load_stage(1, 1);

    float acc[4][4][4];
#pragma unroll
    for (int i = 0; i < 4; i++)
#pragma unroll
        for (int j = 0; j < 4; j++)
#pragma unroll
            for (int k = 0; k < 4; k++) acc[i][j][k] = 0.f;

    int a_row_b = warp_mi * 64 + (lane & 15);
    int a_cadd = lane >> 4;
    int b_row_b = warp_ni * 32 + (lane & 7) + ((lane >> 4) << 3);
    int b_cadd = (lane >> 3) & 1;

    for (int kt = 0; kt < KT; kt++) {
        if (kt >= KT - 1) cpwait<0>(); else cpwait<1>();
        __syncthreads();
        if (kt + 2 < KT) load_stage((kt + 2) % 3, kt + 2);

        uint32_t sA = sbase + (kt % 3) * STG;
        uint32_t sB = sA + 16384;
#pragma unroll
        for (int ks = 0; ks < 4; ks++) {
            int kc = ks * 2;
            uint32_t a[4][4];
#pragma unroll
            for (int mi = 0; mi < 4; mi++) {
                int row = a_row_b + mi * 16;
                int cs = (kc + a_cadd) ^ (row & 7);
                ldm_x4(a[mi], sA + row * 128 + cs * 16);
            }
            uint32_t bf[2][4];
#pragma unroll
            for (int j2 = 0; j2 < 2; j2++) {
                int row = b_row_b + j2 * 16;
                int cs = (kc + b_cadd) ^ (row & 7);
                ldm_x4(bf[j2], sB + row * 128 + cs * 16);
            }
#pragma unroll
            for (int mi = 0; mi < 4; mi++)
#pragma unroll
                for (int ni = 0; ni < 4; ni++)
                    mma_h(acc[mi][ni], a[mi], &bf[ni >> 1][(ni & 1) * 2]);
        }
    }

    int g = lane >> 2, tq = lane & 3;
    float gm = gamma[0];
    float2 iv[4];
#pragma unroll
    for (int ni = 0; ni < 4; ni++) {
        int ncol = n0 + warp_ni * 32 + ni * 8 + 2 * tq;
        float2 sv = *(const float2*)&g_sum[b * NPOS + ncol];
        iv[ni].x = 1.f / sv.x;
        iv[ni].y = 1.f / sv.y;
    }

#pragma unroll
    for (int mi = 0; mi < 4; mi++) {
        int c_r0 = c0 + warp_mi * 64 + mi * 16 + g;
        int c_r1 = c_r0 + 8;
#pragma unroll
        for (int ni = 0; ni < 4; ni++) {
            int ncol = n0 + warp_ni * 32 + ni * 8 + 2 * tq;
            size_t off0 = ((size_t)b * C + c_r0) * NPOS + ncol;
            size_t off1 = ((size_t)b * C + c_r1) * NPOS + ncol;
            float2 xv0 = *(const float2*)&x[off0];
            float2 xv1 = *(const float2*)&x[off1];
            float2 o0, o1;
            o0.x = gm * iv[ni].x * acc[mi][ni][0] + xv0.x;
            o0.y = gm * iv[ni].y * acc[mi][ni][1] + xv0.y;
            o1.x = gm * iv[ni].x * acc[mi][ni][2] + xv1.x;
            o1.y = gm * iv[ni].y * acc[mi][ni][3] + xv1.y;
            *(float2*)&out[off0] = o0;
            *(float2*)&out[off1] = o1;
        }
    }
}

// ---------------------------------------------------------------------------
extern "C" void kernel_launch(void* const* d_in, const int* in_sizes, int n_in,
                              void* d_out, int out_size)
{
    const float* x     = (const float*)d_in[0];
    const float* Wq    = (const float*)d_in[1];
    const float* bq    = (const float*)d_in[2];
    const float* Wk    = (const float*)d_in[3];
    const float* bk    = (const float*)d_in[4];
    const float* Wv    = (const float*)d_in[5];
    const float* bv    = (const float*)d_in[6];
    const float* gamma = (const float*)d_in[7];
    float* out = (float*)d_out;

    cudaFuncSetAttribute(proj_all_kernel,
                         cudaFuncAttributeMaxDynamicSharedMemorySize, 65536);
    cudaFuncSetAttribute(energy_kernel,
                         cudaFuncAttributeMaxDynamicSharedMemorySize, 49152);
    cudaFuncSetAttribute(out_kernel,
                         cudaFuncAttributeMaxDynamicSharedMemorySize, 98304);

    cvt_x_kernel<<<(int)((size_t)BATCH * C * NPOS / 4 / 256), 256>>>(x);

    proj_all_kernel<<<dim3(NPOS / 128, 5, BATCH), 256, 65536>>>(Wv, bv, Wq, bq, Wk, bk);

    energy_kernel<<<dim3(NPOS / (128 * MB), NPOS / 128, BATCH), 256, 49152>>>();

    out_kernel<<<dim3(C / 128, NPOS / 128, BATCH), 256, 98304>>>(x, gamma, out);
}

// round 15
// speedup vs baseline: 1.2234x; 1.0284x over previous
#include <cuda_runtime.h>
#include <cstdint>

#define BATCH 4
#define C 512
#define CQ 64
#define NPOS 4096

#define LOG2E 1.4426950408889634f
#define PSHIFT 4.0f
#define MB 4                       // m-tiles per energy CTA

// ---------------- scratch (device globals) ----------------------------------
__device__ uint16_t g_qbT[(size_t)BATCH * NPOS * CQ];   // [b][n][o] f16, pre-scaled log2e
__device__ uint16_t g_kbT[(size_t)BATCH * NPOS * CQ];   // [b][m][o] f16
__device__ uint16_t g_v [(size_t)BATCH * C * NPOS];     // [b][c][m] f16
__device__ uint16_t g_P [(size_t)BATCH * NPOS * NPOS];  // [b][n][m] f16 2^(E'-4)
__device__ uint16_t g_xb[(size_t)BATCH * C * NPOS];     // [b][c][n] f16
__device__ float    g_sum[BATCH * NPOS];

// ---------------- helpers ----------------------------------------------------
__device__ __forceinline__ unsigned smem_u32(const void* p) {
    return (unsigned)__cvta_generic_to_shared(p);
}
__device__ __forceinline__ void cpa16(unsigned s, const void* g) {
    asm volatile("cp.async.cg.shared.global [%0], [%1], 16;\n" :: "r"(s), "l"(g));
}
__device__ __forceinline__ void cpcommit() { asm volatile("cp.async.commit_group;\n" ::); }
template <int n>
__device__ __forceinline__ void cpwait() { asm volatile("cp.async.wait_group %0;\n" :: "n"(n)); }

__device__ __forceinline__ uint32_t hpack(float lo, float hi) {
    uint32_t u;
    asm("cvt.rn.f16x2.f32 %0, %1, %2;" : "=r"(u) : "f"(hi), "f"(lo));
    return u;
}
__device__ __forceinline__ uint16_t h16of(float x) {
    uint16_t h;
    asm("cvt.rn.f16.f32 %0, %1;" : "=h"(h) : "f"(x));
    return h;
}
__device__ __forceinline__ float2 h2f2(uint32_t h) {
    float2 f;
    asm("{\n\t.reg .f16 l,h;\n\tmov.b32 {l,h}, %2;\n\t"
        "cvt.f32.f16 %0, l;\n\tcvt.f32.f16 %1, h;\n\t}"
        : "=f"(f.x), "=f"(f.y) : "r"(h));
    return f;
}
__device__ __forceinline__ uint32_t ex2h2(uint32_t x) {
    uint32_t d;
    asm("ex2.approx.f16x2 %0, %1;" : "=r"(d) : "r"(x));
    return d;
}
__device__ __forceinline__ void ldm_x4(uint32_t* r, uint32_t addr) {
    asm volatile("ldmatrix.sync.aligned.m8n8.x4.shared.b16 {%0,%1,%2,%3}, [%4];"
        : "=r"(r[0]), "=r"(r[1]), "=r"(r[2]), "=r"(r[3]) : "r"(addr));
}
__device__ __forceinline__ void ldm_x4_t(uint32_t* r, uint32_t addr) {
    asm volatile("ldmatrix.sync.aligned.m8n8.x4.trans.shared.b16 {%0,%1,%2,%3}, [%4];"
        : "=r"(r[0]), "=r"(r[1]), "=r"(r[2]), "=r"(r[3]) : "r"(addr));
}
__device__ __forceinline__ void mma_h(float* d, const uint32_t* a, const uint32_t* b) {
    asm volatile("mma.sync.aligned.m16n8k16.row.col.f32.f16.f16.f32 "
        "{%0,%1,%2,%3}, {%4,%5,%6,%7}, {%8,%9}, {%0,%1,%2,%3};"
        : "+f"(d[0]), "+f"(d[1]), "+f"(d[2]), "+f"(d[3])
        : "r"(a[0]), "r"(a[1]), "r"(a[2]), "r"(a[3]), "r"(b[0]), "r"(b[1]));
}
// f16 accumulator variant: D packed as 2x h2 regs
__device__ __forceinline__ void mma_hh(uint32_t* d, const uint32_t* a, const uint32_t* b) {
    asm volatile("mma.sync.aligned.m16n8k16.row.col.f16.f16.f16.f16 "
        "{%0,%1}, {%2,%3,%4,%5}, {%6,%7}, {%0,%1};"
        : "+r"(d[0]), "+r"(d[1])
        : "r"(a[0]), "r"(a[1]), "r"(a[2]), "r"(a[3]), "r"(b[0]), "r"(b[1]));
}

extern __shared__ __align__(16) char smem[];

// ---------------------------------------------------------------------------
// x (fp32) -> g_xb (f16); first 16384 threads also zero g_sum.
__global__ void cvt_x_kernel(const float* __restrict__ x) {
    int t = blockIdx.x * 256 + threadIdx.x;
    if (t < BATCH * NPOS) g_sum[t] = 0.f;
    size_t i = (size_t)t * 4;
    float4 v = *(const float4*)&x[i];
    uint2 o;
    o.x = hpack(v.x, v.y);
    o.y = hpack(v.z, v.w);
    *(uint2*)&g_xb[i] = o;
}

// ---------------------------------------------------------------------------
// Merged projection kernel (f16 mma). blockIdx.y: 0..3 = V c-blocks, 4 = q/k.
// ---------------------------------------------------------------------------
__global__ __launch_bounds__(256) void proj_all_kernel(
    const float* __restrict__ Wv, const float* __restrict__ bv,
    const float* __restrict__ Wq, const float* __restrict__ bq,
    const float* __restrict__ Wk, const float* __restrict__ bk)
{
    uint32_t sbase = smem_u32(smem);

    int tid = threadIdx.x, lane = tid & 31, wid = tid >> 5;
    int warp_mi = wid >> 2;
    int warp_ni = wid & 3;
    int b = blockIdx.z;
    int n0 = blockIdx.x * 128;
    int yb = blockIdx.y;
    bool is_qk = (yb == 4);
    int c0 = yb * 128;

    const uint16_t* X = g_xb + (size_t)b * C * NPOS;
    const int KT = C / 64;

    float aw[4][8];
    auto ldgA = [&](int kt) {
#pragma unroll
        for (int i = 0; i < 4; i++) {
            int idx = tid + i * 256;
            int r = idx >> 3, c = idx & 7;
            const float* src;
            if (is_qk)
                src = (r < 64) ? Wq + (size_t)r * C + kt * 64 + c * 8
                               : Wk + (size_t)(r - 64) * C + kt * 64 + c * 8;
            else
                src = Wv + (size_t)(c0 + r) * C + kt * 64 + c * 8;
            float4 v0 = *(const float4*)src;
            float4 v1 = *(const float4*)(src + 4);
            aw[i][0] = v0.x; aw[i][1] = v0.y; aw[i][2] = v0.z; aw[i][3] = v0.w;
            aw[i][4] = v1.x; aw[i][5] = v1.y; aw[i][6] = v1.z; aw[i][7] = v1.w;
        }
    };
    auto stsA = [&](int s) {
#pragma unroll
        for (int i = 0; i < 4; i++) {
            int idx = tid + i * 256;
            int r = idx >> 3, c = idx & 7;
            int cs = c ^ (r & 7);
            uint4 o;
            o.x = hpack(aw[i][0], aw[i][1]);
            o.y = hpack(aw[i][2], aw[i][3]);
            o.z = hpack(aw[i][4], aw[i][5]);
            o.w = hpack(aw[i][6], aw[i][7]);
            *(uint4*)(smem + s * 32768 + r * 128 + cs * 16) = o;
        }
    };
    auto cpaB = [&](int kt, int s) {
#pragma unroll
        for (int i = 0; i < 4; i++) {
            int idx = tid + i * 256;
            int r = idx >> 4, c = idx & 15;
            int cs = (c & 8) | ((c & 7) ^ (r & 7));
            cpa16(sbase + s * 32768 + 16384 + r * 256 + cs * 16,
                  X + (size_t)(kt * 64 + r) * NPOS + n0 + c * 8);
        }
        cpcommit();
    };

    float acc[4][4][4];
#pragma unroll
    for (int i = 0; i < 4; i++)
#pragma unroll
        for (int j = 0; j < 4; j++)
#pragma unroll
            for (int k = 0; k < 4; k++) acc[i][j][k] = 0.f;

    ldgA(0);
    cpaB(0, 0);
    stsA(0);

    for (int kt = 0; kt < KT; kt++) {
        cpwait<0>();
        __syncthreads();
        if (kt + 1 < KT) {
            cpaB(kt + 1, (kt + 1) & 1);
            ldgA(kt + 1);
        }
        uint32_t sA = sbase + (kt & 1) * 32768;
        uint32_t sB = sA + 16384;
#pragma unroll
        for (int ks = 0; ks < 4; ks++) {
            uint32_t a[4][4];
#pragma unroll
            for (int mi = 0; mi < 4; mi++) {
                int row = warp_mi * 64 + mi * 16 + (lane & 15);
                int ch = ks * 2 + (lane >> 4);
                int cs = ch ^ (row & 7);
                ldm_x4(a[mi], sA + row * 128 + cs * 16);
            }
            uint32_t bf[2][4];
#pragma unroll
            for (int nb = 0; nb < 2; nb++) {
                int krow = ks * 16 + (lane & 7) + ((lane >> 3) & 1) * 8;
                int nch = warp_ni * 4 + nb * 2 + (lane >> 4);
                int cs = (nch & 8) | ((nch & 7) ^ (krow & 7));
                ldm_x4_t(bf[nb], sB + krow * 256 + cs * 16);
            }
#pragma unroll
            for (int mi = 0; mi < 4; mi++)
#pragma unroll
                for (int ni = 0; ni < 4; ni++)
                    mma_h(acc[mi][ni], a[mi], &bf[ni >> 1][(ni & 1) * 2]);
        }
        if (kt + 1 < KT) stsA((kt + 1) & 1);
    }

    int g = lane >> 2, tq = lane & 3;
    if (is_qk) {
        uint16_t* Y = (warp_mi == 0 ? g_qbT : g_kbT) + (size_t)b * NPOS * CQ;
        float scale = (warp_mi == 0) ? LOG2E : 1.0f;
#pragma unroll
        for (int mi = 0; mi < 4; mi++) {
            int o0 = mi * 16 + g;
            int o1 = o0 + 8;
            float bv0 = (warp_mi == 0) ? bq[o0] : bk[o0];
            float bv1 = (warp_mi == 0) ? bq[o1] : bk[o1];
#pragma unroll
            for (int ni = 0; ni < 4; ni++) {
                int ncol = n0 + warp_ni * 32 + ni * 8 + 2 * tq;
                Y[(size_t)ncol * CQ + o0]       = h16of((acc[mi][ni][0] + bv0) * scale);
                Y[(size_t)(ncol + 1) * CQ + o0] = h16of((acc[mi][ni][1] + bv0) * scale);
                Y[(size_t)ncol * CQ + o1]       = h16of((acc[mi][ni][2] + bv1) * scale);
                Y[(size_t)(ncol + 1) * CQ + o1] = h16of((acc[mi][ni][3] + bv1) * scale);
            }
        }
    } else {
        uint16_t* Vout = g_v + (size_t)b * C * NPOS;
#pragma unroll
        for (int mi = 0; mi < 4; mi++) {
            int c_r0 = c0 + warp_mi * 64 + mi * 16 + g;
            int c_r1 = c_r0 + 8;
            float bv0 = bv[c_r0], bv1 = bv[c_r1];
#pragma unroll
            for (int ni = 0; ni < 4; ni++) {
                int ncol = n0 + warp_ni * 32 + ni * 8 + 2 * tq;
                *(uint32_t*)&Vout[(size_t)c_r0 * NPOS + ncol] =
                    hpack(acc[mi][ni][0] + bv0, acc[mi][ni][1] + bv0);
                *(uint32_t*)&Vout[(size_t)c_r1 * NPOS + ncol] =
                    hpack(acc[mi][ni][2] + bv1, acc[mi][ni][3] + bv1);
            }
        }
    }
}

// ---------------------------------------------------------------------------
// Energy (f16 mma, persistent m-loop, 2 CTAs/SM).
// ---------------------------------------------------------------------------
__global__ __launch_bounds__(256, 2) void energy_kernel()
{
    uint32_t sA = smem_u32(smem);
    uint32_t sB0 = sA + 16384;

    int tid = threadIdx.x, lane = tid & 31, wid = tid >> 5;
    int warp_mi = wid >> 2;
    int warp_ni = wid & 3;
    int b = blockIdx.z;
    int n0 = blockIdx.y * 128;
    int mbase = blockIdx.x * (MB * 128);

    const uint16_t* Aq = g_qbT + ((size_t)b * NPOS + n0) * CQ;
    const uint16_t* Bk = g_kbT + (size_t)b * NPOS * CQ;

    auto cpaB = [&](int m0, uint32_t dst) {
#pragma unroll
        for (int i = 0; i < 4; i++) {
            int idx = i * 256 + tid;
            int r = idx >> 3, c = idx & 7;
            int cs = c ^ (r & 7);
            cpa16(dst + r * 128 + cs * 16, Bk + (size_t)(m0 + r) * CQ + c * 8);
        }
        cpcommit();
    };

#pragma unroll
    for (int i = 0; i < 4; i++) {
        int idx = i * 256 + tid;
        int r = idx >> 3, c = idx & 7;
        int cs = c ^ (r & 7);
        cpa16(sA + r * 128 + cs * 16, Aq + (size_t)r * CQ + c * 8);
    }
    cpaB(mbase, sB0);

    int a_row_b = warp_mi * 64 + (lane & 15);
    int a_cadd = lane >> 4;
    int b_row_b = warp_ni * 32 + (lane & 7) + ((lane >> 4) << 3);
    int b_cadd = (lane >> 3) & 1;
    int g = lane >> 2, tq = lane & 3;

    uint16_t* Pout = g_P + (size_t)b * NPOS * NPOS;
    uint32_t onesb[2] = {0x3C003C00u, 0x3C003C00u};
    float ssum[4][4];
#pragma unroll
    for (int i = 0; i < 4; i++)
#pragma unroll
        for (int k = 0; k < 4; k++) ssum[i][k] = 0.f;

    for (int mt = 0; mt < MB; mt++) {
        int m0 = mbase + mt * 128;
        uint32_t sB = sB0 + (mt & 1) * 16384;

        cpwait<0>();
        __syncthreads();
        if (mt + 1 < MB)
            cpaB(m0 + 128, sB0 + ((mt + 1) & 1) * 16384);

        float acc[4][4][4];
#pragma unroll
        for (int i = 0; i < 4; i++)
#pragma unroll
            for (int j = 0; j < 4; j++)
#pragma unroll
                for (int k = 0; k < 4; k++) acc[i][j][k] = 0.f;

#pragma unroll
        for (int ks = 0; ks < 4; ks++) {
            int kc = ks * 2;
            uint32_t a[4][4];
#pragma unroll
            for (int mi = 0; mi < 4; mi++) {
                int row = a_row_b + mi * 16;
                int cs = (kc + a_cadd) ^ (row & 7);
                ldm_x4(a[mi], sA + row * 128 + cs * 16);
            }
            uint32_t bf[2][4];
#pragma unroll
            for (int j2 = 0; j2 < 2; j2++) {
                int row = b_row_b + j2 * 16;
                int cs = (kc + b_cadd) ^ (row & 7);
                ldm_x4(bf[j2], sB + row * 128 + cs * 16);
            }
#pragma unroll
            for (int mi = 0; mi < 4; mi++)
#pragma unroll
                for (int ni = 0; ni < 4; ni++)
                    mma_h(acc[mi][ni], a[mi], &bf[ni >> 1][(ni & 1) * 2]);
        }

#pragma unroll
        for (int mi = 0; mi < 4; mi++) {
            int r0 = n0 + warp_mi * 64 + mi * 16 + g;
            int r1 = r0 + 8;
            uint32_t e01[4], e23[4];
#pragma unroll
            for (int ni = 0; ni < 4; ni++) {
                e01[ni] = ex2h2(hpack(acc[mi][ni][0] - PSHIFT, acc[mi][ni][1] - PSHIFT));
                e23[ni] = ex2h2(hpack(acc[mi][ni][2] - PSHIFT, acc[mi][ni][3] - PSHIFT));
                int col = m0 + warp_ni * 32 + ni * 8 + 2 * tq;
                *(uint32_t*)&Pout[(size_t)r0 * NPOS + col] = e01[ni];
                *(uint32_t*)&Pout[(size_t)r1 * NPOS + col] = e23[ni];
            }
            uint32_t A0[4] = {e01[0], e23[0], e01[1], e23[1]};
            uint32_t A1[4] = {e01[2], e23[2], e01[3], e23[3]};
            mma_h(ssum[mi], A0, onesb);
            mma_h(ssum[mi], A1, onesb);
        }
        __syncthreads();
    }

    if (tq == 0) {
        float* SUM = g_sum + b * NPOS;
#pragma unroll
        for (int mi = 0; mi < 4; mi++) {
            int r0 = n0 + warp_mi * 64 + mi * 16 + g;
            atomicAdd(&SUM[r0], ssum[mi][0]);
            atomicAdd(&SUM[r0 + 8], ssum[mi][2]);
        }
    }
}

// ---------------------------------------------------------------------------
// Out (f16 mma, f16 ACC, 128c x 256n tile, 2-stage, 2 CTAs/SM):
// D[c][n] = sum_m V[c][m]*P[n][m]; out = gamma*(1/sum[n])*D + x.
// Warp tile 64x64 (2x4 warps): 8 ldmatrix per 32 mma (was 6/16) -> smem
// read per MMA cut 1.5x. f16 accumulators keep acc at 64 regs.
// smem: 2 stages x (16KB A + 32KB B) = 96KB.
// ---------------------------------------------------------------------------
__global__ __launch_bounds__(256, 2) void out_kernel(
    const float* __restrict__ x, const float* __restrict__ gamma,
    float* __restrict__ out)
{
    uint32_t sbase = smem_u32(smem);

    int tid = threadIdx.x, lane = tid & 31, wid = tid >> 5;
    int warp_mi = wid >> 2;        // c-dim (2 x 64)
    int warp_ni = wid & 3;         // n-dim (4 x 64)
    int b = blockIdx.z;
    int n0 = blockIdx.y * 256, c0 = blockIdx.x * 128;

    const uint16_t* V = g_v + ((size_t)b * C + c0) * NPOS;
    const uint16_t* P = g_P + ((size_t)b * NPOS + n0) * NPOS;

    const int KT = NPOS / 64;      // 64
    const int STG = 49152;         // 16KB A + 32KB B per stage

    auto load_stage = [&](int s, int kt) {
        int mb = kt * 64;
        uint32_t st = sbase + s * STG;
#pragma unroll
        for (int i = 0; i < 4; i++) {          // A: 128 rows x 128B
            int idx = i * 256 + tid;
            int r = idx >> 3, c = idx & 7;
            int cs = c ^ (r & 7);
            cpa16(st + r * 128 + cs * 16, V + (size_t)r * NPOS + mb + c * 8);
        }
#pragma unroll
        for (int i = 0; i < 8; i++) {          // B: 256 rows x 128B
            int idx = i * 256 + tid;
            int r = idx >> 3, c = idx & 7;
            int cs = c ^ (r & 7);
            cpa16(st + 16384 + r * 128 + cs * 16, P + (size_t)r * NPOS + mb + c * 8);
        }
        cpcommit();
    };

    load_stage(0, 0);

    uint32_t acc[2][8][2];         // f16x2 accumulators: mi 2? no -> [4]?  (see below)
    // warp tile 64(c) x 64(n): mi = 4 (m16 each), ni = 8 (n8 each)
    uint32_t acch[4][8][2];
#pragma unroll
    for (int i = 0; i < 4; i++)
#pragma unroll
        for (int j = 0; j < 8; j++) {
            acch[i][j][0] = 0u;
            acch[i][j][1] = 0u;
        }

    int a_row_b = warp_mi * 64 + (lane & 15);
    int a_cadd = lane >> 4;
    int b_row_b = warp_ni * 64 + (lane & 7) + ((lane >> 4) << 3);
    int b_cadd = (lane >> 3) & 1;

    for (int kt = 0; kt < KT; kt++) {
        if (kt + 1 < KT) {
            load_stage((kt + 1) & 1, kt + 1);
            cpwait<1>();
        } else {
            cpwait<0>();
        }
        __syncthreads();

        uint32_t sA = sbase + (kt & 1) * STG;
        uint32_t sB = sA + 16384;
#pragma unroll
        for (int ks = 0; ks < 4; ks++) {
            int kc = ks * 2;
            uint32_t a[4][4];
#pragma unroll
            for (int mi = 0; mi < 4; mi++) {
                int row = a_row_b + mi * 16;
                int cs = (kc + a_cadd) ^ (row & 7);
                ldm_x4(a[mi], sA + row * 128 + cs * 16);
            }
            uint32_t bf[4][4];
#pragma unroll
            for (int j2 = 0; j2 < 4; j2++) {
                int row = b_row_b + j2 * 16;
                int cs = (kc + b_cadd) ^ (row & 7);
                ldm_x4(bf[j2], sB + row * 128 + cs * 16);
            }
#pragma unroll
            for (int mi = 0; mi < 4; mi++)
#pragma unroll
                for (int ni = 0; ni < 8; ni++)
                    mma_hh(acch[mi][ni], a[mi], &bf[ni >> 1][(ni & 1) * 2]);
        }
        __syncthreads();           // free both stage slots before next overwrite
    }

    int g = lane >> 2, tq = lane & 3;
    float gm = gamma[0];
    float2 iv[8];
#pragma unroll
    for (int ni = 0; ni < 8; ni++) {
        int ncol = n0 + warp_ni * 64 + ni * 8 + 2 * tq;
        float2 sv = *(const float2*)&g_sum[b * NPOS + ncol];
        iv[ni].x = 1.f / sv.x;
        iv[ni].y = 1.f / sv.y;
    }

#pragma unroll
    for (int mi = 0; mi < 4; mi++) {
        int c_r0 = c0 + warp_mi * 64 + mi * 16 + g;
        int c_r1 = c_r0 + 8;
#pragma unroll
        for (int ni = 0; ni < 8; ni++) {
            int ncol = n0 + warp_ni * 64 + ni * 8 + 2 * tq;
            size_t off0 = ((size_t)b * C + c_r0) * NPOS + ncol;
            size_t off1 = ((size_t)b * C + c_r1) * NPOS + ncol;
            float2 d0 = h2f2(acch[mi][ni][0]);
            float2 d1 = h2f2(acch[mi][ni][1]);
            float2 xv0 = *(const float2*)&x[off0];
            float2 xv1 = *(const float2*)&x[off1];
            float2 o0, o1;
            o0.x = gm * iv[ni].x * d0.x + xv0.x;
            o0.y = gm * iv[ni].y * d0.y + xv0.y;
            o1.x = gm * iv[ni].x * d1.x + xv1.x;
            o1.y = gm * iv[ni].y * d1.y + xv1.y;
            *(float2*)&out[off0] = o0;
            *(float2*)&out[off1] = o1;
        }
    }
}

// ---------------------------------------------------------------------------
extern "C" void kernel_launch(void* const* d_in, const int* in_sizes, int n_in,
                              void* d_out, int out_size)
{
    const float* x     = (const float*)d_in[0];
    const float* Wq    = (const float*)d_in[1];
    const float* bq    = (const float*)d_in[2];
    const float* Wk    = (const float*)d_in[3];
    const float* bk    = (const float*)d_in[4];
    const float* Wv    = (const float*)d_in[5];
    const float* bv    = (const float*)d_in[6];
    const float* gamma = (const float*)d_in[7];
    float* out = (float*)d_out;

    cudaFuncSetAttribute(proj_all_kernel,
                         cudaFuncAttributeMaxDynamicSharedMemorySize, 65536);
    cudaFuncSetAttribute(energy_kernel,
                         cudaFuncAttributeMaxDynamicSharedMemorySize, 49152);
    cudaFuncSetAttribute(out_kernel,
                         cudaFuncAttributeMaxDynamicSharedMemorySize, 98304);

    cvt_x_kernel<<<(int)((size_t)BATCH * C * NPOS / 4 / 256), 256>>>(x);

    proj_all_kernel<<<dim3(NPOS / 128, 5, BATCH), 256, 65536>>>(Wv, bv, Wq, bq, Wk, bk);

    energy_kernel<<<dim3(NPOS / (128 * MB), NPOS / 128, BATCH), 256, 49152>>>();

    out_kernel<<<dim3(C / 128, NPOS / 256, BATCH), 256, 98304>>>(x, gamma, out);
}